// round 11
// baseline (speedup 1.0000x reference)
#include <cuda_runtime.h>
#include <cuda_bf16.h>
#include <cuda_fp16.h>
#include <cstdint>

#define HDIM 64
#define NODE_DIM 92
#define EDGE_DIM 41
#define KD 169            // 2H + EDGE_DIM
#define OUTC 128          // 2H
#define PRED_H 128
#define BN_EPS 1e-5f
#define MAX_NODES 100000
#define MAX_EDGES 1600000
#define MAX_GRAPHS 4096
#define MAX_CONV 3

#define NCH 11            // k16 chunks (K=176 padded)
#define ASTRIDE 92        // A smem row stride (u32 words): 88 data + 4 pad
#define AWORDS (128 * ASTRIDE)               // 47104 B per buffer
#define BU2    (NCH * 16 * 32)               // 5632 uint2 = 45056 B
#define SMEM_WORDS (2 * AWORDS + 2 * BU2)    // 139264 B -> 1 CTA/SM, 512 thr

// ------------------------- device scratch ------------------------------------
__device__ float  g_h[MAX_NODES * HDIM];
__device__ __half g_zh[(size_t)MAX_EDGES * OUTC];   // CSR-permuted pre-BN activations
__device__ float  g_sum[OUTC];
__device__ float  g_sumsq[OUTC];
__device__ float  g_coef[2 * OUTC];
__device__ float  g_pool[MAX_GRAPHS * HDIM];
__device__ float  g_cnt[MAX_GRAPHS];
__device__ __align__(16) uint2    g_bfrag[MAX_CONV * BU2];
__device__ __align__(16) uint32_t g_hh[(size_t)MAX_NODES * 32];   // h as fp16x2
__device__ __align__(16) uint32_t g_efh[(size_t)MAX_EDGES * 24];  // ef as fp16x2
// CSR
__device__ int g_rowstart[MAX_NODES + 1];
__device__ int g_cursor[MAX_NODES];
__device__ int g_epos[MAX_EDGES];                   // edge -> CSR position
__device__ int g_bsum[1024];

// ------------------------- helpers ------------------------------------------
__device__ __forceinline__ float fsig(float x) {
    float t;
    asm("tanh.approx.f32 %0, %1;" : "=f"(t) : "f"(0.5f * x));
    return fmaf(0.5f, t, 0.5f);
}
__device__ __forceinline__ float fsp(float x) {
    float t = __expf(-fabsf(x));
    return fmaxf(x, 0.f) + __logf(1.f + t);
}

__device__ __forceinline__ void mma16816(float* d, const uint32_t* a, uint2 b) {
    asm volatile("mma.sync.aligned.m16n8k16.row.col.f32.f16.f16.f32 "
                 "{%0,%1,%2,%3}, {%4,%5,%6,%7}, {%8,%9}, {%0,%1,%2,%3};"
                 : "+f"(d[0]), "+f"(d[1]), "+f"(d[2]), "+f"(d[3])
                 : "r"(a[0]), "r"(a[1]), "r"(a[2]), "r"(a[3]), "r"(b.x), "r"(b.y));
}
__device__ __forceinline__ void ldsm4(uint32_t* a, uint32_t addr) {
    asm volatile("ldmatrix.sync.aligned.m8n8.x4.shared.b16 {%0,%1,%2,%3}, [%4];"
                 : "=r"(a[0]), "=r"(a[1]), "=r"(a[2]), "=r"(a[3]) : "r"(addr));
}
__device__ __forceinline__ uint32_t smem_u32(const void* p) {
    uint32_t a;
    asm("{ .reg .u64 t; cvta.to.shared.u64 t, %1; cvt.u32.u64 %0, t; }" : "=r"(a) : "l"(p));
    return a;
}
__device__ __forceinline__ void cp16(uint32_t dst, const void* src, int sz) {
    asm volatile("cp.async.cg.shared.global [%0], [%1], 16, %2;"
                 :: "r"(dst), "l"(src), "r"(sz) : "memory");
}
#define CP_COMMIT() asm volatile("cp.async.commit_group;" ::: "memory")
#define CP_WAIT1()  asm volatile("cp.async.wait_group 1;" ::: "memory")

// ------------------------- 1. node embedding (writes g_h + g_hh) ------------
__global__ void __launch_bounds__(256)
emb_kernel(const float* __restrict__ nf, const float* __restrict__ Wm,
           const float* __restrict__ b, int nNodes) {
    __shared__ float sW[NODE_DIM * HDIM];
    __shared__ float sXn[8][NODE_DIM];
    for (int i = threadIdx.x; i < NODE_DIM * HDIM; i += 256) sW[i] = Wm[i];
    __syncthreads();
    int wid = threadIdx.x >> 5, lane = threadIdx.x & 31;
    int gw = (blockIdx.x * 256 + threadIdx.x) >> 5;
    int nW = (gridDim.x * 256) >> 5;
    float b0 = b[2 * lane], b1 = b[2 * lane + 1];
    for (int n = gw; n < nNodes; n += nW) {
        __syncwarp();
        for (int k = lane; k < NODE_DIM; k += 32) sXn[wid][k] = nf[(size_t)n * NODE_DIM + k];
        __syncwarp();
        float a0 = b0, a1 = b1;
        #pragma unroll 4
        for (int k = 0; k < NODE_DIM; k++) {
            float xv = sXn[wid][k];
            float2 w = ((const float2*)sW)[k * 32 + lane];
            a0 = fmaf(xv, w.x, a0);
            a1 = fmaf(xv, w.y, a1);
        }
        ((float2*)(g_h + (size_t)n * HDIM))[lane] = make_float2(a0, a1);
        __half2 h = __floats2half2_rn(a0, a1);
        g_hh[(size_t)n * 32 + lane] = *reinterpret_cast<uint32_t*>(&h);
    }
}

// efsplit also zeroes the CSR cursor (runs before hist)
__global__ void __launch_bounds__(256)
efsplit_kernel(const float* __restrict__ ef, int nEdges, int nNodes) {
    long long idx = (long long)blockIdx.x * 256 + threadIdx.x;
    if (idx < nNodes) g_cursor[(int)idx] = 0;
    if (idx >= (long long)nEdges * 24) return;
    int w = (int)(idx % 24);
    long long e = idx / 24;
    int c = 2 * w;
    float f0 = 0.f, f1 = 0.f;
    if (c < EDGE_DIM)     f0 = ef[e * EDGE_DIM + c];
    if (c + 1 < EDGE_DIM) f1 = ef[e * EDGE_DIM + c + 1];
    __half2 h = __floats2half2_rn(f0, f1);
    g_efh[idx] = *reinterpret_cast<uint32_t*>(&h);
}

// ------------------------- CSR build -----------------------------------------
__global__ void hist_kernel(const int* __restrict__ ei, int nEdges) {
    int e = blockIdx.x * 256 + threadIdx.x;
    if (e < nEdges) atomicAdd(&g_cursor[ei[e]], 1);
}
__global__ void __launch_bounds__(1024)
scan1_kernel(int n) {
    __shared__ int wsum[32];
    int tid = threadIdx.x;
    int i = blockIdx.x * 1024 + tid;
    int c = (i < n) ? g_cursor[i] : 0;
    int v = c;
    #pragma unroll
    for (int o = 1; o < 32; o <<= 1) {
        int t = __shfl_up_sync(0xffffffffu, v, o);
        if ((tid & 31) >= o) v += t;
    }
    if ((tid & 31) == 31) wsum[tid >> 5] = v;
    __syncthreads();
    if (tid < 32) {
        int s = wsum[tid];
        #pragma unroll
        for (int o = 1; o < 32; o <<= 1) {
            int t = __shfl_up_sync(0xffffffffu, s, o);
            if (tid >= o) s += t;
        }
        wsum[tid] = s;
    }
    __syncthreads();
    int incl = v + ((tid >= 32) ? wsum[(tid >> 5) - 1] : 0);
    if (i < n) g_rowstart[i] = incl - c;
    if (tid == 1023) g_bsum[blockIdx.x] = incl;
}
__global__ void __launch_bounds__(1024)
scan2_kernel(int nb) {
    __shared__ int wsum[32];
    int tid = threadIdx.x;
    int v = (tid < nb) ? g_bsum[tid] : 0;
    #pragma unroll
    for (int o = 1; o < 32; o <<= 1) {
        int t = __shfl_up_sync(0xffffffffu, v, o);
        if ((tid & 31) >= o) v += t;
    }
    if ((tid & 31) == 31) wsum[tid >> 5] = v;
    __syncthreads();
    if (tid < 32) {
        int s = wsum[tid];
        #pragma unroll
        for (int o = 1; o < 32; o <<= 1) {
            int t = __shfl_up_sync(0xffffffffu, s, o);
            if (tid >= o) s += t;
        }
        wsum[tid] = s;
    }
    __syncthreads();
    int incl = v + ((tid >= 32) ? wsum[(tid >> 5) - 1] : 0);
    if (tid < nb) g_bsum[tid] = incl;
}
__global__ void __launch_bounds__(1024)
scan3_kernel(int n, int nEdges) {
    int i = blockIdx.x * 1024 + threadIdx.x;
    if (i >= n) return;
    int off = blockIdx.x ? g_bsum[blockIdx.x - 1] : 0;
    int ex = g_rowstart[i] + off;
    g_rowstart[i] = ex;
    g_cursor[i] = ex;
    if (i == n - 1) g_rowstart[n] = nEdges;
}
__global__ void scatter_kernel(const int* __restrict__ ei, int nEdges) {
    int e = blockIdx.x * 256 + threadIdx.x;
    if (e >= nEdges) return;
    g_epos[e] = atomicAdd(&g_cursor[ei[e]], 1);
}

// ------------------------- 2a. B fragments, all layers ----------------------
__global__ void __launch_bounds__(256)
bfrag_kernel(const float* __restrict__ W, int total) {
    int idx = blockIdx.x * 256 + threadIdx.x;
    if (idx >= total) return;
    int l = idx / BU2, r = idx % BU2;
    int lane = r & 31;
    int nt   = (r >> 5) & 15;
    int bi   = r >> 9;                // 0..10
    const float* Wl = W + (size_t)l * KD * OUTC;
    int n    = nt * 8 + (lane >> 2);
    int k0   = bi * 16 + (lane & 3) * 2;
    uint32_t out[2];
    #pragma unroll
    for (int half = 0; half < 2; half++) {
        float w0 = 0.f, w1 = 0.f;
        int ka = k0 + half * 8, kb = ka + 1;
        if (ka < KD) w0 = Wl[ka * OUTC + n];
        if (kb < KD) w1 = Wl[kb * OUTC + n];
        __half2 h = __floats2half2_rn(w0, w1);
        out[half] = *reinterpret_cast<uint32_t*>(&h);
    }
    g_bfrag[idx] = make_uint2(out[0], out[1]);
}

// ------------------------- 2b. conv edge GEMM (512 thr, dbl-buffered A) -----
// threads 0..255: h rows (2 per row); threads 256..511: ef (2 per row)
__device__ __forceinline__ void gatherAsync(uint32_t* sA, const int* __restrict__ ei,
                                            int nEdges, int t, int nTiles) {
    if (t < nTiles) {
        int j = threadIdx.x;
        if (j < 256) {
            int row = j >> 1, half = j & 1;
            int e = (t << 7) + row;
            bool valid = e < nEdges;
            int ec = valid ? e : 0;
            int sz = valid ? 16 : 0;
            int node = ei[half ? nEdges + ec : ec];
            const char* hs = (const char*)(g_hh + (size_t)node * 32);
            uint32_t dh = smem_u32(sA + row * ASTRIDE + half * 32);
            #pragma unroll
            for (int i = 0; i < 8; i++) cp16(dh + i * 16, hs + i * 16, sz);
        } else {
            int k = j - 256;
            int row = k >> 1, eh = k & 1;
            int e = (t << 7) + row;
            bool valid = e < nEdges;
            int ec = valid ? e : 0;
            int sz = valid ? 16 : 0;
            const char* es = (const char*)(g_efh + (size_t)ec * 24 + eh * 12);
            uint32_t de = smem_u32(sA + row * ASTRIDE + 64 + eh * 12);
            #pragma unroll
            for (int i = 0; i < 3; i++) cp16(de + i * 16, es + i * 16, sz);
        }
    }
    CP_COMMIT();    // empty group when t >= nTiles keeps wait_group counting valid
}

__global__ void __launch_bounds__(512, 1)
conv_mma_kernel(const int* __restrict__ ei, int l, int nEdges, int nTiles) {
    extern __shared__ uint32_t sm[];
    uint32_t* sA0 = sm;
    uint32_t* sA1 = sm + AWORDS;
    uint2*    sB  = (uint2*)(sm + 2 * AWORDS);

    const int tid = threadIdx.x, wid = tid >> 5, lane = tid & 31;
    const int q = lane & 3, r8 = lane >> 2;
    const int wm = wid & 3, wn = wid >> 2;   // wn 0..3: 32-col slice

    const int grid = gridDim.x;
    gatherAsync(sA0, ei, nEdges, blockIdx.x, nTiles);
    gatherAsync(sA1, ei, nEdges, blockIdx.x + grid, nTiles);
    const uint2* bf = g_bfrag + (size_t)l * BU2;
    for (int i = tid; i < BU2 / 2; i += 512)
        ((uint4*)sB)[i] = ((const uint4*)bf)[i];

    float ssum[8], ssq[8];
    #pragma unroll
    for (int j = 0; j < 8; j++) { ssum[j] = 0.f; ssq[j] = 0.f; }

    CP_WAIT1();          // sA0 ready (sA1 may still be in flight)
    __syncthreads();

    // ldmatrix base addresses (per buffer): row = wm*32 + (lane&15), second
    // 16B column block for lanes 16-31
    const uint32_t aoff = (uint32_t)((wm * 32 + (lane & 15)) * ASTRIDE * 4 +
                                     ((lane >> 4) << 4));
    const uint32_t aA0 = smem_u32(sA0) + aoff;
    const uint32_t aA1 = smem_u32(sA1) + aoff;
    const uint2* bBase = sB + (wn * 4) * 32 + lane;

    int pp = 0;
    for (int t = blockIdx.x; t < nTiles; t += grid) {
        const uint32_t aAddr = pp ? aA1 : aA0;
        const int e0 = t << 7;

        int pe[4];
        #pragma unroll
        for (int mt = 0; mt < 2; mt++)
            #pragma unroll
            for (int hf = 0; hf < 2; hf++) {
                int e = e0 + wm * 32 + mt * 16 + hf * 8 + r8;
                pe[mt * 2 + hf] = (e < nEdges) ? __ldg(&g_epos[e]) : -1;
            }

        float acc[2][4][4];
        #pragma unroll
        for (int mt = 0; mt < 2; mt++)
            #pragma unroll
            for (int n4 = 0; n4 < 4; n4++)
                #pragma unroll
                for (int jj = 0; jj < 4; jj++) acc[mt][n4][jj] = 0.f;

        #pragma unroll 1
        for (int bi = 0; bi < NCH; bi++) {
            uint2 b[4];
            const uint2* bp = bBase + bi * 512;
            #pragma unroll
            for (int n4 = 0; n4 < 4; n4++) b[n4] = bp[n4 * 32];
            uint32_t a0[4], a1[4];
            ldsm4(a0, aAddr + bi * 32);
            ldsm4(a1, aAddr + 16 * ASTRIDE * 4 + bi * 32);
            #pragma unroll
            for (int n4 = 0; n4 < 4; n4++) {
                mma16816(acc[0][n4], a0, b[n4]);
                mma16816(acc[1][n4], a1, b[n4]);
            }
        }

        // ---- stats + z write (CSR-permuted) ----
        #pragma unroll
        for (int mt = 0; mt < 2; mt++)
            #pragma unroll
            for (int n4 = 0; n4 < 4; n4++) {
                float c0 = acc[mt][n4][0], c1 = acc[mt][n4][1];
                float c2 = acc[mt][n4][2], c3 = acc[mt][n4][3];
                ssum[n4 * 2]     += c0 + c2;   ssum[n4 * 2 + 1] += c1 + c3;
                ssq[n4 * 2]      += c0 * c0 + c2 * c2;
                ssq[n4 * 2 + 1]  += c1 * c1 + c3 * c3;
            }
        #pragma unroll
        for (int mt = 0; mt < 2; mt++)
            #pragma unroll
            for (int hf = 0; hf < 2; hf++) {
                int p = pe[mt * 2 + hf];
                if (p >= 0) {
                    __half* base = g_zh + (size_t)p * OUTC + wn * 32 + 2 * q;
                    #pragma unroll
                    for (int n4 = 0; n4 < 4; n4++) {
                        __half2 h = __floats2half2_rn(acc[mt][n4][2 * hf],
                                                      acc[mt][n4][2 * hf + 1]);
                        *(uint32_t*)(base + n4 * 8) = *reinterpret_cast<uint32_t*>(&h);
                    }
                }
            }

        __syncthreads();                                      // done reading buf pp
        gatherAsync(pp ? sA1 : sA0, ei, nEdges, t + 2 * grid, nTiles);
        CP_WAIT1();                                           // buf pp^1 complete
        __syncthreads();                                      // visible to all
        pp ^= 1;
    }

    // ---- finalize BN stats ----
    #pragma unroll
    for (int j = 0; j < 8; j++) {
        #pragma unroll
        for (int ofs = 4; ofs < 32; ofs <<= 1) {
            ssum[j] += __shfl_xor_sync(0xffffffffu, ssum[j], ofs);
            ssq[j]  += __shfl_xor_sync(0xffffffffu, ssq[j], ofs);
        }
    }
    if (lane < 4) {
        #pragma unroll
        for (int n4 = 0; n4 < 4; n4++)
            #pragma unroll
            for (int jj = 0; jj < 2; jj++) {
                int col = wn * 32 + n4 * 8 + 2 * lane + jj;
                atomicAdd(&g_sum[col],   ssum[n4 * 2 + jj]);
                atomicAdd(&g_sumsq[col], ssq[n4 * 2 + jj]);
            }
    }
}

// ------------------------- 3. BN coefficients (self-zeroing stats) ----------
__global__ void bn_coef_kernel(const float* __restrict__ gamma,
                               const float* __restrict__ beta, float invE) {
    int c = threadIdx.x;
    float s = g_sum[c], ss = g_sumsq[c];
    float mean = s * invE;
    float var  = fmaf(-mean, mean, ss * invE);
    float a    = gamma[c] * rsqrtf(var + BN_EPS);
    g_coef[c]        = a;
    g_coef[OUTC + c] = fmaf(-mean, a, beta[c]);
    g_sum[c] = 0.f;
    g_sumsq[c] = 0.f;
}

// ------------------------- 4. CSR gate: streaming z -------------------------
__global__ void __launch_bounds__(256)
csr_gate_kernel(const int* __restrict__ gidArr, int nNodes, int doPool) {
    int gw = blockIdx.x * 8 + (threadIdx.x >> 5);
    if (gw >= nNodes) return;
    int lane = threadIdx.x & 31;

    float sa0 = g_coef[2 * lane],             sa1 = g_coef[2 * lane + 1];
    float ha0 = g_coef[OUTC + 2 * lane],      ha1 = g_coef[OUTC + 2 * lane + 1];
    float sb0 = g_coef[64 + 2 * lane],        sb1 = g_coef[64 + 2 * lane + 1];
    float hb0 = g_coef[OUTC + 64 + 2 * lane], hb1 = g_coef[OUTC + 64 + 2 * lane + 1];

    int beg = g_rowstart[gw], end = g_rowstart[gw + 1];
    float a0 = 0.f, a1 = 0.f;
    const uint32_t* zr = (const uint32_t*)(g_zh) + (size_t)beg * 64;
    #pragma unroll 4
    for (int i = beg; i < end; i++, zr += 64) {
        uint32_t A = zr[lane], B = zr[32 + lane];
        __half2 ha = *reinterpret_cast<__half2*>(&A);
        __half2 hb = *reinterpret_cast<__half2*>(&B);
        float na0 = fmaf(__low2float(ha),  sa0, ha0);
        float na1 = fmaf(__high2float(ha), sa1, ha1);
        float nb0 = fmaf(__low2float(hb),  sb0, hb0);
        float nb1 = fmaf(__high2float(hb), sb1, hb1);
        a0 += fsig(na0) * fsp(nb0);
        a1 += fsig(na1) * fsp(nb1);
    }
    float2* hp = (float2*)(g_h + (size_t)gw * HDIM) + lane;
    float2 hv = *hp;
    hv.x += a0; hv.y += a1;
    *hp = hv;
    __half2 hh = __floats2half2_rn(hv.x, hv.y);
    g_hh[(size_t)gw * 32 + lane] = *reinterpret_cast<uint32_t*>(&hh);
    if (doPool) {
        int g = gidArr[gw];
        float* pr = g_pool + (size_t)g * HDIM + 2 * lane;
        asm volatile("red.global.add.v2.f32 [%0], {%1, %2};"
                     :: "l"(pr), "f"(hv.x), "f"(hv.y) : "memory");
        if (lane == 0) atomicAdd(&g_cnt[g], 1.0f);
    }
}

// ------------------------- 5. prediction head (self-zeroing pool) -----------
__global__ void __launch_bounds__(PRED_H)
head_kernel(const float* __restrict__ fcW, const float* __restrict__ fcb,
            const float* __restrict__ outW, const float* __restrict__ outb,
            float* __restrict__ out) {
    __shared__ float sp[HDIM];
    __shared__ float red[PRED_H];
    int g = blockIdx.x, t = threadIdx.x;
    if (t < HDIM) {
        float c = g_cnt[g];
        sp[t] = g_pool[(size_t)g * HDIM + t] / fmaxf(c, 1.0f);
    }
    __syncthreads();
    float acc = fcb[t];
    #pragma unroll
    for (int k = 0; k < HDIM; k++) acc = fmaf(sp[k], fcW[k * PRED_H + t], acc);
    red[t] = fmaxf(acc, 0.f) + log1pf(expf(-fabsf(acc)));
    red[t] *= outW[t];
    __syncthreads();
    for (int sft = PRED_H / 2; sft > 0; sft >>= 1) {
        if (t < sft) red[t] += red[t + sft];
        __syncthreads();
    }
    if (t == 0) out[g] = red[0] + outb[0];
    __syncthreads();
    if (t < HDIM) g_pool[(size_t)g * HDIM + t] = 0.f;
    if (t == HDIM) g_cnt[g] = 0.f;
}

// ------------------------- launch -------------------------------------------
extern "C" void kernel_launch(void* const* d_in, const int* in_sizes, int n_in,
                              void* d_out, int out_size) {
    const float* node_feats = (const float*)d_in[0];
    const int*   edge_index = (const int*)d_in[1];
    const float* edge_feats = (const float*)d_in[2];
    const int*   graph_id   = (const int*)d_in[3];
    const float* emb_W      = (const float*)d_in[4];
    const float* emb_b      = (const float*)d_in[5];
    const float* conv_W     = (const float*)d_in[6];
    // d_in[7] = conv_b: zeros; constant bias cancels exactly in BN.
    const float* bn_gamma   = (const float*)d_in[8];
    const float* bn_beta    = (const float*)d_in[9];
    const float* fc_W       = (const float*)d_in[10];
    const float* fc_b       = (const float*)d_in[11];
    const float* out_W      = (const float*)d_in[12];
    const float* out_b      = (const float*)d_in[13];

    int nNodes  = in_sizes[0] / NODE_DIM;
    int nEdges  = in_sizes[1] / 2;
    int nConv   = in_sizes[6] / (KD * OUTC);

    int nsm = 148;
    cudaDeviceGetAttribute(&nsm, cudaDevAttrMultiProcessorCount, 0);

    size_t convSmem = (size_t)SMEM_WORDS * 4;   // 139264 B
    cudaFuncSetAttribute(conv_mma_kernel,
                         cudaFuncAttributeMaxDynamicSharedMemorySize, (int)convSmem);

    emb_kernel<<<2048, 256>>>(node_feats, emb_W, emb_b, nNodes);
    {
        long long tot = (long long)nEdges * 24;
        efsplit_kernel<<<(int)((tot + 255) / 256), 256>>>(edge_feats, nEdges, nNodes);
    }

    // ---- CSR build (edge_index constant across layers) ----
    int eb = (nEdges + 255) / 256;
    int nb1 = (nNodes + 1023) / 1024;
    hist_kernel<<<eb, 256>>>(edge_index, nEdges);
    scan1_kernel<<<nb1, 1024>>>(nNodes);
    scan2_kernel<<<1, 1024>>>(nb1);
    scan3_kernel<<<nb1, 1024>>>(nNodes, nEdges);
    scatter_kernel<<<eb, 256>>>(edge_index, nEdges);

    // ---- all-layer B fragments ----
    bfrag_kernel<<<(nConv * BU2 + 255) / 256, 256>>>(conv_W, nConv * BU2);

    int nTiles = (nEdges + 127) / 128;
    float invE = 1.0f / (float)nEdges;
    int gateBlocks = (nNodes + 7) / 8;
    for (int l = 0; l < nConv; l++) {
        conv_mma_kernel<<<nsm, 512, convSmem>>>(edge_index, l, nEdges, nTiles);
        bn_coef_kernel<<<1, OUTC>>>(bn_gamma + l * OUTC, bn_beta + l * OUTC, invE);
        csr_gate_kernel<<<gateBlocks, 256>>>(graph_id, nNodes, l == nConv - 1);
    }

    head_kernel<<<out_size, PRED_H>>>(fc_W, fc_b, out_W, out_b, (float*)d_out);
}

// round 12
// speedup vs baseline: 1.0911x; 1.0911x over previous
#include <cuda_runtime.h>
#include <cuda_bf16.h>
#include <cuda_fp16.h>
#include <cstdint>

#define HDIM 64
#define NODE_DIM 92
#define EDGE_DIM 41
#define KD 169            // 2H + EDGE_DIM
#define OUTC 128          // 2H
#define PRED_H 128
#define BN_EPS 1e-5f
#define MAX_NODES 100000
#define MAX_EDGES 1600000
#define MAX_GRAPHS 4096
#define MAX_CONV 3
#define NPW 15            // nodes per gate warp

#define NCH 11            // k16 chunks (K=176 padded)
#define ASTRIDE 92        // A smem row stride (u32 words): 88 data + 4 pad
#define AWORDS (128 * ASTRIDE)               // 47104 B
#define BU2    (NCH * 16 * 32)               // 5632 uint2 = 45056 B
#define SMEM_WORDS (AWORDS + 2 * BU2)        // 92160 B -> 2 CTAs/SM

// ------------------------- device scratch ------------------------------------
__device__ float  g_h[MAX_NODES * HDIM];
__device__ __half g_zh[(size_t)MAX_EDGES * OUTC];   // CSR-permuted pre-BN activations
__device__ float  g_sum[OUTC];
__device__ float  g_sumsq[OUTC];
__device__ float  g_coef[2 * OUTC];
__device__ float  g_pool[MAX_GRAPHS * HDIM];
__device__ float  g_cnt[MAX_GRAPHS];
__device__ __align__(16) uint2    g_bfrag[MAX_CONV * BU2];
__device__ __align__(16) uint32_t g_hh[(size_t)MAX_NODES * 32];   // h as fp16x2
__device__ __align__(16) uint32_t g_efh[(size_t)MAX_EDGES * 24];  // ef as fp16x2
// CSR
__device__ int g_rowstart[MAX_NODES + 1];
__device__ int g_cursor[MAX_NODES];
__device__ int g_epos[MAX_EDGES];                   // edge -> CSR position
__device__ int g_bsum[1024];

// ------------------------- helpers ------------------------------------------
__device__ __forceinline__ float fsig(float x) {
    float t;
    asm("tanh.approx.f32 %0, %1;" : "=f"(t) : "f"(0.5f * x));
    return fmaf(0.5f, t, 0.5f);
}
__device__ __forceinline__ float fsp(float x) {
    float t = __expf(-fabsf(x));
    return fmaxf(x, 0.f) + __logf(1.f + t);
}

__device__ __forceinline__ void mma16816(float* d, const uint32_t* a, uint2 b) {
    asm volatile("mma.sync.aligned.m16n8k16.row.col.f32.f16.f16.f32 "
                 "{%0,%1,%2,%3}, {%4,%5,%6,%7}, {%8,%9}, {%0,%1,%2,%3};"
                 : "+f"(d[0]), "+f"(d[1]), "+f"(d[2]), "+f"(d[3])
                 : "r"(a[0]), "r"(a[1]), "r"(a[2]), "r"(a[3]), "r"(b.x), "r"(b.y));
}
__device__ __forceinline__ uint32_t smem_u32(const void* p) {
    uint32_t a;
    asm("{ .reg .u64 t; cvta.to.shared.u64 t, %1; cvt.u32.u64 %0, t; }" : "=r"(a) : "l"(p));
    return a;
}
__device__ __forceinline__ void cp16(uint32_t dst, const void* src, int sz) {
    asm volatile("cp.async.cg.shared.global [%0], [%1], 16, %2;"
                 :: "r"(dst), "l"(src), "r"(sz) : "memory");
}
#define CP_COMMIT() asm volatile("cp.async.commit_group;" ::: "memory")
#define CP_WAIT0()  asm volatile("cp.async.wait_group 0;" ::: "memory")

// ------------------------- 1. node embedding (writes g_h + g_hh) ------------
__global__ void __launch_bounds__(256)
emb_kernel(const float* __restrict__ nf, const float* __restrict__ Wm,
           const float* __restrict__ b, int nNodes) {
    __shared__ float sW[NODE_DIM * HDIM];
    __shared__ float sXn[8][NODE_DIM];
    for (int i = threadIdx.x; i < NODE_DIM * HDIM; i += 256) sW[i] = Wm[i];
    __syncthreads();
    int wid = threadIdx.x >> 5, lane = threadIdx.x & 31;
    int gw = (blockIdx.x * 256 + threadIdx.x) >> 5;
    int nW = (gridDim.x * 256) >> 5;
    float b0 = b[2 * lane], b1 = b[2 * lane + 1];
    for (int n = gw; n < nNodes; n += nW) {
        __syncwarp();
        for (int k = lane; k < NODE_DIM; k += 32) sXn[wid][k] = nf[(size_t)n * NODE_DIM + k];
        __syncwarp();
        float a0 = b0, a1 = b1;
        #pragma unroll 4
        for (int k = 0; k < NODE_DIM; k++) {
            float xv = sXn[wid][k];
            float2 w = ((const float2*)sW)[k * 32 + lane];
            a0 = fmaf(xv, w.x, a0);
            a1 = fmaf(xv, w.y, a1);
        }
        ((float2*)(g_h + (size_t)n * HDIM))[lane] = make_float2(a0, a1);
        __half2 h = __floats2half2_rn(a0, a1);
        g_hh[(size_t)n * 32 + lane] = *reinterpret_cast<uint32_t*>(&h);
    }
}

__global__ void __launch_bounds__(256)
efsplit_kernel(const float* __restrict__ ef, int nEdges, int nNodes) {
    long long idx = (long long)blockIdx.x * 256 + threadIdx.x;
    if (idx < nNodes) g_cursor[(int)idx] = 0;
    if (idx >= (long long)nEdges * 24) return;
    int w = (int)(idx % 24);
    long long e = idx / 24;
    int c = 2 * w;
    float f0 = 0.f, f1 = 0.f;
    if (c < EDGE_DIM)     f0 = ef[e * EDGE_DIM + c];
    if (c + 1 < EDGE_DIM) f1 = ef[e * EDGE_DIM + c + 1];
    __half2 h = __floats2half2_rn(f0, f1);
    g_efh[idx] = *reinterpret_cast<uint32_t*>(&h);
}

// ------------------------- CSR build -----------------------------------------
__global__ void hist_kernel(const int* __restrict__ ei, int nEdges) {
    int e = blockIdx.x * 256 + threadIdx.x;
    if (e < nEdges) atomicAdd(&g_cursor[ei[e]], 1);
}
__global__ void __launch_bounds__(1024)
scan1_kernel(int n) {
    __shared__ int wsum[32];
    int tid = threadIdx.x;
    int i = blockIdx.x * 1024 + tid;
    int c = (i < n) ? g_cursor[i] : 0;
    int v = c;
    #pragma unroll
    for (int o = 1; o < 32; o <<= 1) {
        int t = __shfl_up_sync(0xffffffffu, v, o);
        if ((tid & 31) >= o) v += t;
    }
    if ((tid & 31) == 31) wsum[tid >> 5] = v;
    __syncthreads();
    if (tid < 32) {
        int s = wsum[tid];
        #pragma unroll
        for (int o = 1; o < 32; o <<= 1) {
            int t = __shfl_up_sync(0xffffffffu, s, o);
            if (tid >= o) s += t;
        }
        wsum[tid] = s;
    }
    __syncthreads();
    int incl = v + ((tid >= 32) ? wsum[(tid >> 5) - 1] : 0);
    if (i < n) g_rowstart[i] = incl - c;
    if (tid == 1023) g_bsum[blockIdx.x] = incl;
}
__global__ void __launch_bounds__(1024)
scan2_kernel(int nb) {
    __shared__ int wsum[32];
    int tid = threadIdx.x;
    int v = (tid < nb) ? g_bsum[tid] : 0;
    #pragma unroll
    for (int o = 1; o < 32; o <<= 1) {
        int t = __shfl_up_sync(0xffffffffu, v, o);
        if ((tid & 31) >= o) v += t;
    }
    if ((tid & 31) == 31) wsum[tid >> 5] = v;
    __syncthreads();
    if (tid < 32) {
        int s = wsum[tid];
        #pragma unroll
        for (int o = 1; o < 32; o <<= 1) {
            int t = __shfl_up_sync(0xffffffffu, s, o);
            if (tid >= o) s += t;
        }
        wsum[tid] = s;
    }
    __syncthreads();
    int incl = v + ((tid >= 32) ? wsum[(tid >> 5) - 1] : 0);
    if (tid < nb) g_bsum[tid] = incl;
}
__global__ void __launch_bounds__(1024)
scan3_kernel(int n, int nEdges) {
    int i = blockIdx.x * 1024 + threadIdx.x;
    if (i >= n) return;
    int off = blockIdx.x ? g_bsum[blockIdx.x - 1] : 0;
    int ex = g_rowstart[i] + off;
    g_rowstart[i] = ex;
    g_cursor[i] = ex;
    if (i == n - 1) g_rowstart[n] = nEdges;
}
__global__ void scatter_kernel(const int* __restrict__ ei, int nEdges) {
    int e = blockIdx.x * 256 + threadIdx.x;
    if (e >= nEdges) return;
    g_epos[e] = atomicAdd(&g_cursor[ei[e]], 1);
}

// ------------------------- 2a. B fragments, all layers ----------------------
__global__ void __launch_bounds__(256)
bfrag_kernel(const float* __restrict__ W, int total) {
    int idx = blockIdx.x * 256 + threadIdx.x;
    if (idx >= total) return;
    int l = idx / BU2, r = idx % BU2;
    int lane = r & 31;
    int nt   = (r >> 5) & 15;
    int bi   = r >> 9;                // 0..10
    const float* Wl = W + (size_t)l * KD * OUTC;
    int n    = nt * 8 + (lane >> 2);
    int k0   = bi * 16 + (lane & 3) * 2;
    uint32_t out[2];
    #pragma unroll
    for (int half = 0; half < 2; half++) {
        float w0 = 0.f, w1 = 0.f;
        int ka = k0 + half * 8, kb = ka + 1;
        if (ka < KD) w0 = Wl[ka * OUTC + n];
        if (kb < KD) w1 = Wl[kb * OUTC + n];
        __half2 h = __floats2half2_rn(w0, w1);
        out[half] = *reinterpret_cast<uint32_t*>(&h);
    }
    g_bfrag[idx] = make_uint2(out[0], out[1]);
}

// ------------------------- 2b. conv edge GEMM (2 CTAs/SM, N-split) ----------
__device__ __forceinline__ void gatherAsync(uint32_t* sA, const int* __restrict__ ei,
                                            int nEdges, int t, int nTiles) {
    if (t >= nTiles) return;
    int j = threadIdx.x;
    int row = j >> 1, half = j & 1;
    int e = (t << 7) + row;
    bool valid = e < nEdges;
    int ec = valid ? e : 0;
    int sz = valid ? 16 : 0;
    int node = ei[half ? nEdges + ec : ec];
    const char* hs = (const char*)(g_hh + (size_t)node * 32);
    uint32_t* rw = sA + row * ASTRIDE;
    uint32_t dh = smem_u32(rw + half * 32);
    #pragma unroll
    for (int i = 0; i < 8; i++) cp16(dh + i * 16, hs + i * 16, sz);
    const char* es = (const char*)(g_efh + (size_t)ec * 24 + half * 12);
    uint32_t de = smem_u32(rw + 64 + half * 12);
    #pragma unroll
    for (int i = 0; i < 3; i++) cp16(de + i * 16, es + i * 16, sz);
    CP_COMMIT();
}

__device__ __forceinline__ void kloop(float acc[2][4][4], const uint32_t* aRow0,
                                      const uint2* bBase, int nh, int q) {
    #pragma unroll 1
    for (int bi = 0; bi < NCH; bi++) {
        uint2 b[4];
        const uint2* bp = bBase + bi * 512 + nh * 128;
        #pragma unroll
        for (int n4 = 0; n4 < 4; n4++) b[n4] = bp[n4 * 32];
        uint32_t a[2][4];
        int aw = bi * 8 + q;
        #pragma unroll
        for (int mt = 0; mt < 2; mt++) {
            const uint32_t* ar = aRow0 + mt * 16 * ASTRIDE;
            a[mt][0] = ar[aw];         a[mt][1] = ar[8 * ASTRIDE + aw];
            a[mt][2] = ar[aw + 4];     a[mt][3] = ar[8 * ASTRIDE + aw + 4];
        }
        #pragma unroll
        for (int n4 = 0; n4 < 4; n4++) {
            mma16816(acc[0][n4], a[0], b[n4]);
            mma16816(acc[1][n4], a[1], b[n4]);
        }
    }
}

__device__ __forceinline__ void statsEpi(float acc[2][4][4], int nh, const int* pe,
                                         int wn, int q, float* ssum, float* ssq) {
    #pragma unroll
    for (int mt = 0; mt < 2; mt++)
        #pragma unroll
        for (int n4 = 0; n4 < 4; n4++) {
            float c0 = acc[mt][n4][0], c1 = acc[mt][n4][1];
            float c2 = acc[mt][n4][2], c3 = acc[mt][n4][3];
            int s = nh * 8 + n4 * 2;
            ssum[s]     += c0 + c2;   ssum[s + 1] += c1 + c3;
            ssq[s]      += c0 * c0 + c2 * c2;
            ssq[s + 1]  += c1 * c1 + c3 * c3;
        }
    #pragma unroll
    for (int mt = 0; mt < 2; mt++)
        #pragma unroll
        for (int hf = 0; hf < 2; hf++) {
            int p = pe[mt * 2 + hf];
            if (p >= 0) {
                __half* base = g_zh + (size_t)p * OUTC + wn * 64 + nh * 32 + 2 * q;
                #pragma unroll
                for (int n4 = 0; n4 < 4; n4++) {
                    __half2 h = __floats2half2_rn(acc[mt][n4][2 * hf],
                                                  acc[mt][n4][2 * hf + 1]);
                    *(uint32_t*)(base + n4 * 8) = *reinterpret_cast<uint32_t*>(&h);
                }
            }
        }
}

__global__ void __launch_bounds__(256, 2)
conv_mma_kernel(const int* __restrict__ ei, int l, int nEdges, int nTiles) {
    extern __shared__ uint32_t sm[];
    uint32_t* sA = sm;
    uint2*    sB = (uint2*)(sm + AWORDS);

    const int tid = threadIdx.x, wid = tid >> 5, lane = tid & 31;
    const int q = lane & 3, r8 = lane >> 2;
    const int wm = wid & 3, wn = wid >> 2;

    gatherAsync(sA, ei, nEdges, blockIdx.x, nTiles);
    const uint2* bf = g_bfrag + (size_t)l * BU2;
    for (int i = tid; i < BU2 / 2; i += 256)
        ((uint4*)sB)[i] = ((const uint4*)bf)[i];

    float ssum[16], ssq[16];
    #pragma unroll
    for (int j = 0; j < 16; j++) { ssum[j] = 0.f; ssq[j] = 0.f; }

    CP_WAIT0();
    __syncthreads();

    const uint32_t* aRow0 = sA + (wm * 32 + r8) * ASTRIDE;
    const uint2*    bBase = sB + (wn * 8) * 32 + lane;

    for (int t = blockIdx.x; t < nTiles; t += gridDim.x) {
        const int e0 = t << 7;
        int pe[4];
        #pragma unroll
        for (int mt = 0; mt < 2; mt++)
            #pragma unroll
            for (int hf = 0; hf < 2; hf++) {
                int e = e0 + wm * 32 + mt * 16 + hf * 8 + r8;
                pe[mt * 2 + hf] = (e < nEdges) ? __ldg(&g_epos[e]) : -1;
            }
        {   // N half 0
            float acc[2][4][4];
            #pragma unroll
            for (int mt = 0; mt < 2; mt++)
                #pragma unroll
                for (int n4 = 0; n4 < 4; n4++)
                    #pragma unroll
                    for (int jj = 0; jj < 4; jj++) acc[mt][n4][jj] = 0.f;
            kloop(acc, aRow0, bBase, 0, q);
            statsEpi(acc, 0, pe, wn, q, ssum, ssq);
        }
        {   // N half 1 (+ prefetch next tile between MMA and epilogue)
            float acc[2][4][4];
            #pragma unroll
            for (int mt = 0; mt < 2; mt++)
                #pragma unroll
                for (int n4 = 0; n4 < 4; n4++)
                    #pragma unroll
                    for (int jj = 0; jj < 4; jj++) acc[mt][n4][jj] = 0.f;
            kloop(acc, aRow0, bBase, 1, q);
            __syncthreads();
            gatherAsync(sA, ei, nEdges, t + gridDim.x, nTiles);
            statsEpi(acc, 1, pe, wn, q, ssum, ssq);
        }
        CP_WAIT0();
        __syncthreads();
    }

    #pragma unroll
    for (int j = 0; j < 16; j++) {
        #pragma unroll
        for (int ofs = 4; ofs < 32; ofs <<= 1) {
            ssum[j] += __shfl_xor_sync(0xffffffffu, ssum[j], ofs);
            ssq[j]  += __shfl_xor_sync(0xffffffffu, ssq[j], ofs);
        }
    }
    if (lane < 4) {
        #pragma unroll
        for (int nh = 0; nh < 2; nh++)
            #pragma unroll
            for (int n4 = 0; n4 < 4; n4++)
                #pragma unroll
                for (int jj = 0; jj < 2; jj++) {
                    int col = wn * 64 + nh * 32 + n4 * 8 + 2 * lane + jj;
                    atomicAdd(&g_sum[col],   ssum[nh * 8 + n4 * 2 + jj]);
                    atomicAdd(&g_sumsq[col], ssq[nh * 8 + n4 * 2 + jj]);
                }
    }
}

// ------------------------- 3. BN coefficients (self-zeroing stats) ----------
__global__ void bn_coef_kernel(const float* __restrict__ gamma,
                               const float* __restrict__ beta, float invE) {
    int c = threadIdx.x;
    float s = g_sum[c], ss = g_sumsq[c];
    float mean = s * invE;
    float var  = fmaf(-mean, mean, ss * invE);
    float a    = gamma[c] * rsqrtf(var + BN_EPS);
    g_coef[c]        = a;
    g_coef[OUTC + c] = fmaf(-mean, a, beta[c]);
    g_sum[c] = 0.f;
    g_sumsq[c] = 0.f;
}

// ------------------------- 4. CSR gate: warp per node RANGE -----------------
__global__ void __launch_bounds__(256)
csr_gate_kernel(const int* __restrict__ gidArr, int nNodes, int doPool) {
    int w = blockIdx.x * 8 + (threadIdx.x >> 5);
    int n0 = w * NPW;
    if (n0 >= nNodes) return;
    int n1 = min(n0 + NPW, nNodes);
    int lane = threadIdx.x & 31;

    float sa0 = g_coef[2 * lane],             sa1 = g_coef[2 * lane + 1];
    float ha0 = g_coef[OUTC + 2 * lane],      ha1 = g_coef[OUTC + 2 * lane + 1];
    float sb0 = g_coef[64 + 2 * lane],        sb1 = g_coef[64 + 2 * lane + 1];
    float hb0 = g_coef[OUTC + 64 + 2 * lane], hb1 = g_coef[OUTC + 64 + 2 * lane + 1];

    int beg = g_rowstart[n0];
    const uint32_t* zr = (const uint32_t*)(g_zh) + (size_t)beg * 64;
    for (int gw = n0; gw < n1; gw++) {
        int end = g_rowstart[gw + 1];
        float a0 = 0.f, a1 = 0.f;
        #pragma unroll 2
        for (int i = beg; i < end; i++, zr += 64) {
            uint32_t A = zr[lane], B = zr[32 + lane];
            __half2 ha = *reinterpret_cast<__half2*>(&A);
            __half2 hb = *reinterpret_cast<__half2*>(&B);
            float na0 = fmaf(__low2float(ha),  sa0, ha0);
            float na1 = fmaf(__high2float(ha), sa1, ha1);
            float nb0 = fmaf(__low2float(hb),  sb0, hb0);
            float nb1 = fmaf(__high2float(hb), sb1, hb1);
            a0 += fsig(na0) * fsp(nb0);
            a1 += fsig(na1) * fsp(nb1);
        }
        beg = end;
        float2* hp = (float2*)(g_h + (size_t)gw * HDIM) + lane;
        float2 hv = *hp;
        hv.x += a0; hv.y += a1;
        *hp = hv;
        __half2 hh = __floats2half2_rn(hv.x, hv.y);
        g_hh[(size_t)gw * 32 + lane] = *reinterpret_cast<uint32_t*>(&hh);
        if (doPool) {
            int g = gidArr[gw];
            float* pr = g_pool + (size_t)g * HDIM + 2 * lane;
            asm volatile("red.global.add.v2.f32 [%0], {%1, %2};"
                         :: "l"(pr), "f"(hv.x), "f"(hv.y) : "memory");
            if (lane == 0) atomicAdd(&g_cnt[g], 1.0f);
        }
    }
}

// ------------------------- 5. prediction head (self-zeroing pool) -----------
__global__ void __launch_bounds__(PRED_H)
head_kernel(const float* __restrict__ fcW, const float* __restrict__ fcb,
            const float* __restrict__ outW, const float* __restrict__ outb,
            float* __restrict__ out) {
    __shared__ float sp[HDIM];
    __shared__ float red[PRED_H];
    int g = blockIdx.x, t = threadIdx.x;
    if (t < HDIM) {
        float c = g_cnt[g];
        sp[t] = g_pool[(size_t)g * HDIM + t] / fmaxf(c, 1.0f);
    }
    __syncthreads();
    float acc = fcb[t];
    #pragma unroll
    for (int k = 0; k < HDIM; k++) acc = fmaf(sp[k], fcW[k * PRED_H + t], acc);
    red[t] = fmaxf(acc, 0.f) + log1pf(expf(-fabsf(acc)));
    red[t] *= outW[t];
    __syncthreads();
    for (int sft = PRED_H / 2; sft > 0; sft >>= 1) {
        if (t < sft) red[t] += red[t + sft];
        __syncthreads();
    }
    if (t == 0) out[g] = red[0] + outb[0];
    __syncthreads();
    if (t < HDIM) g_pool[(size_t)g * HDIM + t] = 0.f;
    if (t == HDIM) g_cnt[g] = 0.f;
}

// ------------------------- launch -------------------------------------------
extern "C" void kernel_launch(void* const* d_in, const int* in_sizes, int n_in,
                              void* d_out, int out_size) {
    const float* node_feats = (const float*)d_in[0];
    const int*   edge_index = (const int*)d_in[1];
    const float* edge_feats = (const float*)d_in[2];
    const int*   graph_id   = (const int*)d_in[3];
    const float* emb_W      = (const float*)d_in[4];
    const float* emb_b      = (const float*)d_in[5];
    const float* conv_W     = (const float*)d_in[6];
    // d_in[7] = conv_b: zeros; constant bias cancels exactly in BN.
    const float* bn_gamma   = (const float*)d_in[8];
    const float* bn_beta    = (const float*)d_in[9];
    const float* fc_W       = (const float*)d_in[10];
    const float* fc_b       = (const float*)d_in[11];
    const float* out_W      = (const float*)d_in[12];
    const float* out_b      = (const float*)d_in[13];

    int nNodes  = in_sizes[0] / NODE_DIM;
    int nEdges  = in_sizes[1] / 2;
    int nConv   = in_sizes[6] / (KD * OUTC);

    int nsm = 148;
    cudaDeviceGetAttribute(&nsm, cudaDevAttrMultiProcessorCount, 0);

    size_t convSmem = (size_t)SMEM_WORDS * 4;   // 92160 B
    cudaFuncSetAttribute(conv_mma_kernel,
                         cudaFuncAttributeMaxDynamicSharedMemorySize, (int)convSmem);

    emb_kernel<<<2048, 256>>>(node_feats, emb_W, emb_b, nNodes);
    {
        long long tot = (long long)nEdges * 24;
        efsplit_kernel<<<(int)((tot + 255) / 256), 256>>>(edge_feats, nEdges, nNodes);
    }

    // ---- CSR build (edge_index constant across layers) ----
    int eb = (nEdges + 255) / 256;
    int nb1 = (nNodes + 1023) / 1024;
    hist_kernel<<<eb, 256>>>(edge_index, nEdges);
    scan1_kernel<<<nb1, 1024>>>(nNodes);
    scan2_kernel<<<1, 1024>>>(nb1);
    scan3_kernel<<<nb1, 1024>>>(nNodes, nEdges);
    scatter_kernel<<<eb, 256>>>(edge_index, nEdges);

    // ---- all-layer B fragments ----
    bfrag_kernel<<<(nConv * BU2 + 255) / 256, 256>>>(conv_W, nConv * BU2);

    int nTiles = (nEdges + 127) / 128;
    float invE = 1.0f / (float)nEdges;
    int gateBlocks = (nNodes + 8 * NPW - 1) / (8 * NPW);
    for (int l = 0; l < nConv; l++) {
        conv_mma_kernel<<<2 * nsm, 256, convSmem>>>(edge_index, l, nEdges, nTiles);
        bn_coef_kernel<<<1, OUTC>>>(bn_gamma + l * OUTC, bn_beta + l * OUTC, invE);
        csr_gate_kernel<<<gateBlocks, 256>>>(graph_id, nNodes, l == nConv - 1);
    }

    head_kernel<<<out_size, PRED_H>>>(fc_W, fc_b, out_W, out_b, (float*)d_out);
}

// round 13
// speedup vs baseline: 1.0947x; 1.0033x over previous
#include <cuda_runtime.h>
#include <cuda_bf16.h>
#include <cuda_fp16.h>
#include <cstdint>

#define HDIM 64
#define NODE_DIM 92
#define EDGE_DIM 41
#define KD 169            // 2H + EDGE_DIM
#define OUTC 128          // 2H
#define PRED_H 128
#define BN_EPS 1e-5f
#define MAX_NODES 100000
#define MAX_EDGES 1600000
#define MAX_GRAPHS 4096
#define MAX_CONV 3

#define NCH 11            // k16 chunks (K=176 padded)
#define ASTRIDE 92        // A smem row stride (u32 words): 88 data + 4 pad
#define AWORDS (128 * ASTRIDE)               // 47104 B
#define BU2    (NCH * 16 * 32)               // 5632 uint2 = 45056 B
#define SMEM_WORDS (AWORDS + 2 * BU2)        // 92160 B -> 2 CTAs/SM

// ------------------------- device scratch ------------------------------------
__device__ float  g_h[MAX_NODES * HDIM];
__device__ __half g_zh[(size_t)MAX_EDGES * OUTC];   // CSR-permuted pre-BN activations
__device__ float  g_sum[OUTC];
__device__ float  g_sumsq[OUTC];
__device__ float  g_coef[2 * OUTC];
__device__ float  g_pool[MAX_GRAPHS * HDIM];
__device__ float  g_cnt[MAX_GRAPHS];
__device__ __align__(16) uint2    g_bfrag[MAX_CONV * BU2];
__device__ __align__(16) uint32_t g_hh[(size_t)MAX_NODES * 32];   // h as fp16x2
__device__ __align__(16) uint32_t g_efh[(size_t)MAX_EDGES * 24];  // ef as fp16x2
// CSR
__device__ int g_rowstart[MAX_NODES + 1];
__device__ int g_cursor[MAX_NODES];
__device__ int g_epos[MAX_EDGES];                   // edge -> CSR position

// ------------------------- helpers ------------------------------------------
__device__ __forceinline__ float fsig(float x) {
    float t;
    asm("tanh.approx.f32 %0, %1;" : "=f"(t) : "f"(0.5f * x));
    return fmaf(0.5f, t, 0.5f);
}
__device__ __forceinline__ float fsp(float x) {
    float t = __expf(-fabsf(x));
    return fmaxf(x, 0.f) + __logf(1.f + t);
}

__device__ __forceinline__ void mma16816(float* d, const uint32_t* a, uint2 b) {
    asm volatile("mma.sync.aligned.m16n8k16.row.col.f32.f16.f16.f32 "
                 "{%0,%1,%2,%3}, {%4,%5,%6,%7}, {%8,%9}, {%0,%1,%2,%3};"
                 : "+f"(d[0]), "+f"(d[1]), "+f"(d[2]), "+f"(d[3])
                 : "r"(a[0]), "r"(a[1]), "r"(a[2]), "r"(a[3]), "r"(b.x), "r"(b.y));
}
__device__ __forceinline__ uint32_t smem_u32(const void* p) {
    uint32_t a;
    asm("{ .reg .u64 t; cvta.to.shared.u64 t, %1; cvt.u32.u64 %0, t; }" : "=r"(a) : "l"(p));
    return a;
}
__device__ __forceinline__ void cp16(uint32_t dst, const void* src, int sz) {
    asm volatile("cp.async.cg.shared.global [%0], [%1], 16, %2;"
                 :: "r"(dst), "l"(src), "r"(sz) : "memory");
}
#define CP_COMMIT() asm volatile("cp.async.commit_group;" ::: "memory")
#define CP_WAIT0()  asm volatile("cp.async.wait_group 0;" ::: "memory")
__device__ __forceinline__ void stcs32(void* p, uint32_t v) {
    asm volatile("st.global.cs.u32 [%0], %1;" :: "l"(p), "r"(v) : "memory");
}
__device__ __forceinline__ uint32_t ldcs32(const void* p) {
    uint32_t v;
    asm volatile("ld.global.cs.u32 %0, [%1];" : "=r"(v) : "l"(p));
    return v;
}

// ------------------------- 1. node embedding (writes g_h + g_hh) ------------
__global__ void __launch_bounds__(256)
emb_kernel(const float* __restrict__ nf, const float* __restrict__ Wm,
           const float* __restrict__ b, int nNodes) {
    __shared__ float sW[NODE_DIM * HDIM];
    __shared__ float sXn[8][NODE_DIM];
    for (int i = threadIdx.x; i < NODE_DIM * HDIM; i += 256) sW[i] = Wm[i];
    __syncthreads();
    int wid = threadIdx.x >> 5, lane = threadIdx.x & 31;
    int gw = (blockIdx.x * 256 + threadIdx.x) >> 5;
    int nW = (gridDim.x * 256) >> 5;
    float b0 = b[2 * lane], b1 = b[2 * lane + 1];
    for (int n = gw; n < nNodes; n += nW) {
        __syncwarp();
        for (int k = lane; k < NODE_DIM; k += 32) sXn[wid][k] = nf[(size_t)n * NODE_DIM + k];
        __syncwarp();
        float a0 = b0, a1 = b1;
        #pragma unroll 4
        for (int k = 0; k < NODE_DIM; k++) {
            float xv = sXn[wid][k];
            float2 w = ((const float2*)sW)[k * 32 + lane];
            a0 = fmaf(xv, w.x, a0);
            a1 = fmaf(xv, w.y, a1);
        }
        ((float2*)(g_h + (size_t)n * HDIM))[lane] = make_float2(a0, a1);
        __half2 h = __floats2half2_rn(a0, a1);
        g_hh[(size_t)n * 32 + lane] = *reinterpret_cast<uint32_t*>(&h);
    }
}

// ------------------------- 2. efsplit + bfrag + cursor-zero (one launch) ----
__global__ void __launch_bounds__(256)
prep_kernel(const float* __restrict__ ef, const float* __restrict__ W,
            int nEdges, int nNodes, int efBlocks, int bfragTotal) {
    if ((int)blockIdx.x >= efBlocks) {
        // ---- bfrag part ----
        int idx = (blockIdx.x - efBlocks) * 256 + threadIdx.x;
        if (idx >= bfragTotal) return;
        int l = idx / BU2, r = idx % BU2;
        int lane = r & 31;
        int nt   = (r >> 5) & 15;
        int bi   = r >> 9;
        const float* Wl = W + (size_t)l * KD * OUTC;
        int n    = nt * 8 + (lane >> 2);
        int k0   = bi * 16 + (lane & 3) * 2;
        uint32_t out[2];
        #pragma unroll
        for (int half = 0; half < 2; half++) {
            float w0 = 0.f, w1 = 0.f;
            int ka = k0 + half * 8, kb = ka + 1;
            if (ka < KD) w0 = Wl[ka * OUTC + n];
            if (kb < KD) w1 = Wl[kb * OUTC + n];
            __half2 h = __floats2half2_rn(w0, w1);
            out[half] = *reinterpret_cast<uint32_t*>(&h);
        }
        g_bfrag[idx] = make_uint2(out[0], out[1]);
        return;
    }
    // ---- efsplit part (+ cursor zero) ----
    long long idx = (long long)blockIdx.x * 256 + threadIdx.x;
    if (idx < nNodes) g_cursor[(int)idx] = 0;
    if (idx >= (long long)nEdges * 24) return;
    int w = (int)(idx % 24);
    long long e = idx / 24;
    int c = 2 * w;
    float f0 = 0.f, f1 = 0.f;
    if (c < EDGE_DIM)     f0 = ef[e * EDGE_DIM + c];
    if (c + 1 < EDGE_DIM) f1 = ef[e * EDGE_DIM + c + 1];
    __half2 h = __floats2half2_rn(f0, f1);
    g_efh[idx] = *reinterpret_cast<uint32_t*>(&h);
}

// ------------------------- CSR build -----------------------------------------
__global__ void hist_kernel(const int* __restrict__ ei, int nEdges) {
    int e = blockIdx.x * 256 + threadIdx.x;
    if (e < nEdges) atomicAdd(&g_cursor[ei[e]], 1);
}

// single-block multi-round exclusive scan of g_cursor[0..n) -> rowstart/cursor
__global__ void __launch_bounds__(1024)
scan_kernel(int n, int nEdges) {
    __shared__ int wsum[32];
    int tid = threadIdx.x;
    int wid = tid >> 5, lane = tid & 31;
    int carry = 0;
    for (int base = 0; base < n; base += 1024) {
        int i = base + tid;
        int c = (i < n) ? g_cursor[i] : 0;
        int v = c;
        #pragma unroll
        for (int o = 1; o < 32; o <<= 1) {
            int t = __shfl_up_sync(0xffffffffu, v, o);
            if (lane >= o) v += t;
        }
        if (lane == 31) wsum[wid] = v;
        __syncthreads();
        if (tid < 32) {
            int s = wsum[tid];
            #pragma unroll
            for (int o = 1; o < 32; o <<= 1) {
                int t = __shfl_up_sync(0xffffffffu, s, o);
                if (tid >= o) s += t;
            }
            wsum[tid] = s;
        }
        __syncthreads();
        int incl = v + (wid ? wsum[wid - 1] : 0);
        if (i < n) {
            int ex = incl - c + carry;
            g_rowstart[i] = ex;
            g_cursor[i]   = ex;
        }
        carry += wsum[31];
        __syncthreads();
    }
    if (tid == 0) g_rowstart[n] = nEdges;
}

__global__ void scatter_kernel(const int* __restrict__ ei, int nEdges) {
    int e = blockIdx.x * 256 + threadIdx.x;
    if (e >= nEdges) return;
    g_epos[e] = atomicAdd(&g_cursor[ei[e]], 1);
}

// ------------------------- conv edge GEMM (2 CTAs/SM, N-split) --------------
__device__ __forceinline__ void gatherAsync(uint32_t* sA, const int* __restrict__ ei,
                                            int nEdges, int t, int nTiles) {
    if (t >= nTiles) return;
    int j = threadIdx.x;
    int row = j >> 1, half = j & 1;
    int e = (t << 7) + row;
    bool valid = e < nEdges;
    int ec = valid ? e : 0;
    int sz = valid ? 16 : 0;
    int node = ei[half ? nEdges + ec : ec];
    const char* hs = (const char*)(g_hh + (size_t)node * 32);
    uint32_t* rw = sA + row * ASTRIDE;
    uint32_t dh = smem_u32(rw + half * 32);
    #pragma unroll
    for (int i = 0; i < 8; i++) cp16(dh + i * 16, hs + i * 16, sz);
    const char* es = (const char*)(g_efh + (size_t)ec * 24 + half * 12);
    uint32_t de = smem_u32(rw + 64 + half * 12);
    #pragma unroll
    for (int i = 0; i < 3; i++) cp16(de + i * 16, es + i * 16, sz);
    CP_COMMIT();
}

__device__ __forceinline__ void kloop(float acc[2][4][4], const uint32_t* aRow0,
                                      const uint2* bBase, int nh, int q) {
    #pragma unroll 1
    for (int bi = 0; bi < NCH; bi++) {
        uint2 b[4];
        const uint2* bp = bBase + bi * 512 + nh * 128;
        #pragma unroll
        for (int n4 = 0; n4 < 4; n4++) b[n4] = bp[n4 * 32];
        uint32_t a[2][4];
        int aw = bi * 8 + q;
        #pragma unroll
        for (int mt = 0; mt < 2; mt++) {
            const uint32_t* ar = aRow0 + mt * 16 * ASTRIDE;
            a[mt][0] = ar[aw];         a[mt][1] = ar[8 * ASTRIDE + aw];
            a[mt][2] = ar[aw + 4];     a[mt][3] = ar[8 * ASTRIDE + aw + 4];
        }
        #pragma unroll
        for (int n4 = 0; n4 < 4; n4++) {
            mma16816(acc[0][n4], a[0], b[n4]);
            mma16816(acc[1][n4], a[1], b[n4]);
        }
    }
}

__device__ __forceinline__ void statsEpi(float acc[2][4][4], int nh, const int* pe,
                                         int wn, int q, float* ssum, float* ssq) {
    #pragma unroll
    for (int mt = 0; mt < 2; mt++)
        #pragma unroll
        for (int n4 = 0; n4 < 4; n4++) {
            float c0 = acc[mt][n4][0], c1 = acc[mt][n4][1];
            float c2 = acc[mt][n4][2], c3 = acc[mt][n4][3];
            int s = nh * 8 + n4 * 2;
            ssum[s]     += c0 + c2;   ssum[s + 1] += c1 + c3;
            ssq[s]      += c0 * c0 + c2 * c2;
            ssq[s + 1]  += c1 * c1 + c3 * c3;
        }
    #pragma unroll
    for (int mt = 0; mt < 2; mt++)
        #pragma unroll
        for (int hf = 0; hf < 2; hf++) {
            int p = pe[mt * 2 + hf];
            if (p >= 0) {
                __half* base = g_zh + (size_t)p * OUTC + wn * 64 + nh * 32 + 2 * q;
                #pragma unroll
                for (int n4 = 0; n4 < 4; n4++) {
                    __half2 h = __floats2half2_rn(acc[mt][n4][2 * hf],
                                                  acc[mt][n4][2 * hf + 1]);
                    stcs32(base + n4 * 8, *reinterpret_cast<uint32_t*>(&h));
                }
            }
        }
}

__global__ void __launch_bounds__(256, 2)
conv_mma_kernel(const int* __restrict__ ei, int l, int nEdges, int nTiles) {
    extern __shared__ uint32_t sm[];
    uint32_t* sA = sm;
    uint2*    sB = (uint2*)(sm + AWORDS);

    const int tid = threadIdx.x, wid = tid >> 5, lane = tid & 31;
    const int q = lane & 3, r8 = lane >> 2;
    const int wm = wid & 3, wn = wid >> 2;

    gatherAsync(sA, ei, nEdges, blockIdx.x, nTiles);
    const uint2* bf = g_bfrag + (size_t)l * BU2;
    for (int i = tid; i < BU2 / 2; i += 256)
        ((uint4*)sB)[i] = ((const uint4*)bf)[i];

    float ssum[16], ssq[16];
    #pragma unroll
    for (int j = 0; j < 16; j++) { ssum[j] = 0.f; ssq[j] = 0.f; }

    CP_WAIT0();
    __syncthreads();

    const uint32_t* aRow0 = sA + (wm * 32 + r8) * ASTRIDE;
    const uint2*    bBase = sB + (wn * 8) * 32 + lane;

    for (int t = blockIdx.x; t < nTiles; t += gridDim.x) {
        const int e0 = t << 7;
        int pe[4];
        #pragma unroll
        for (int mt = 0; mt < 2; mt++)
            #pragma unroll
            for (int hf = 0; hf < 2; hf++) {
                int e = e0 + wm * 32 + mt * 16 + hf * 8 + r8;
                pe[mt * 2 + hf] = (e < nEdges) ? __ldg(&g_epos[e]) : -1;
            }
        {   // N half 0
            float acc[2][4][4];
            #pragma unroll
            for (int mt = 0; mt < 2; mt++)
                #pragma unroll
                for (int n4 = 0; n4 < 4; n4++)
                    #pragma unroll
                    for (int jj = 0; jj < 4; jj++) acc[mt][n4][jj] = 0.f;
            kloop(acc, aRow0, bBase, 0, q);
            statsEpi(acc, 0, pe, wn, q, ssum, ssq);
        }
        {   // N half 1 (+ prefetch next tile between MMA and epilogue)
            float acc[2][4][4];
            #pragma unroll
            for (int mt = 0; mt < 2; mt++)
                #pragma unroll
                for (int n4 = 0; n4 < 4; n4++)
                    #pragma unroll
                    for (int jj = 0; jj < 4; jj++) acc[mt][n4][jj] = 0.f;
            kloop(acc, aRow0, bBase, 1, q);
            __syncthreads();
            gatherAsync(sA, ei, nEdges, t + gridDim.x, nTiles);
            statsEpi(acc, 1, pe, wn, q, ssum, ssq);
        }
        CP_WAIT0();
        __syncthreads();
    }

    #pragma unroll
    for (int j = 0; j < 16; j++) {
        #pragma unroll
        for (int ofs = 4; ofs < 32; ofs <<= 1) {
            ssum[j] += __shfl_xor_sync(0xffffffffu, ssum[j], ofs);
            ssq[j]  += __shfl_xor_sync(0xffffffffu, ssq[j], ofs);
        }
    }
    if (lane < 4) {
        #pragma unroll
        for (int nh = 0; nh < 2; nh++)
            #pragma unroll
            for (int n4 = 0; n4 < 4; n4++)
                #pragma unroll
                for (int jj = 0; jj < 2; jj++) {
                    int col = wn * 64 + nh * 32 + n4 * 8 + 2 * lane + jj;
                    atomicAdd(&g_sum[col],   ssum[nh * 8 + n4 * 2 + jj]);
                    atomicAdd(&g_sumsq[col], ssq[nh * 8 + n4 * 2 + jj]);
                }
    }
}

// ------------------------- BN coefficients (self-zeroing stats) -------------
__global__ void bn_coef_kernel(const float* __restrict__ gamma,
                               const float* __restrict__ beta, float invE) {
    int c = threadIdx.x;
    float s = g_sum[c], ss = g_sumsq[c];
    float mean = s * invE;
    float var  = fmaf(-mean, mean, ss * invE);
    float a    = gamma[c] * rsqrtf(var + BN_EPS);
    g_coef[c]        = a;
    g_coef[OUTC + c] = fmaf(-mean, a, beta[c]);
    g_sum[c] = 0.f;
    g_sumsq[c] = 0.f;
}

// ------------------------- CSR gate: streaming z (warp per node) ------------
__global__ void __launch_bounds__(256)
csr_gate_kernel(const int* __restrict__ gidArr, int nNodes, int doPool) {
    int gw = blockIdx.x * 8 + (threadIdx.x >> 5);
    if (gw >= nNodes) return;
    int lane = threadIdx.x & 31;

    float sa0 = g_coef[2 * lane],             sa1 = g_coef[2 * lane + 1];
    float ha0 = g_coef[OUTC + 2 * lane],      ha1 = g_coef[OUTC + 2 * lane + 1];
    float sb0 = g_coef[64 + 2 * lane],        sb1 = g_coef[64 + 2 * lane + 1];
    float hb0 = g_coef[OUTC + 64 + 2 * lane], hb1 = g_coef[OUTC + 64 + 2 * lane + 1];

    int beg = g_rowstart[gw], end = g_rowstart[gw + 1];
    float a0 = 0.f, a1 = 0.f;
    const uint32_t* zr = (const uint32_t*)(g_zh) + (size_t)beg * 64;
    #pragma unroll 2
    for (int i = beg; i < end; i++, zr += 64) {
        uint32_t A = ldcs32(zr + lane);
        uint32_t B = ldcs32(zr + 32 + lane);
        __half2 ha = *reinterpret_cast<__half2*>(&A);
        __half2 hb = *reinterpret_cast<__half2*>(&B);
        float na0 = fmaf(__low2float(ha),  sa0, ha0);
        float na1 = fmaf(__high2float(ha), sa1, ha1);
        float nb0 = fmaf(__low2float(hb),  sb0, hb0);
        float nb1 = fmaf(__high2float(hb), sb1, hb1);
        a0 += fsig(na0) * fsp(nb0);
        a1 += fsig(na1) * fsp(nb1);
    }
    float2* hp = (float2*)(g_h + (size_t)gw * HDIM) + lane;
    float2 hv = *hp;
    hv.x += a0; hv.y += a1;
    *hp = hv;
    __half2 hh = __floats2half2_rn(hv.x, hv.y);
    g_hh[(size_t)gw * 32 + lane] = *reinterpret_cast<uint32_t*>(&hh);
    if (doPool) {
        int g = gidArr[gw];
        float* pr = g_pool + (size_t)g * HDIM + 2 * lane;
        asm volatile("red.global.add.v2.f32 [%0], {%1, %2};"
                     :: "l"(pr), "f"(hv.x), "f"(hv.y) : "memory");
        if (lane == 0) atomicAdd(&g_cnt[g], 1.0f);
    }
}

// ------------------------- prediction head (self-zeroing pool) --------------
__global__ void __launch_bounds__(PRED_H)
head_kernel(const float* __restrict__ fcW, const float* __restrict__ fcb,
            const float* __restrict__ outW, const float* __restrict__ outb,
            float* __restrict__ out) {
    __shared__ float sp[HDIM];
    __shared__ float red[PRED_H];
    int g = blockIdx.x, t = threadIdx.x;
    if (t < HDIM) {
        float c = g_cnt[g];
        sp[t] = g_pool[(size_t)g * HDIM + t] / fmaxf(c, 1.0f);
    }
    __syncthreads();
    float acc = fcb[t];
    #pragma unroll
    for (int k = 0; k < HDIM; k++) acc = fmaf(sp[k], fcW[k * PRED_H + t], acc);
    red[t] = fmaxf(acc, 0.f) + log1pf(expf(-fabsf(acc)));
    red[t] *= outW[t];
    __syncthreads();
    for (int sft = PRED_H / 2; sft > 0; sft >>= 1) {
        if (t < sft) red[t] += red[t + sft];
        __syncthreads();
    }
    if (t == 0) out[g] = red[0] + outb[0];
    __syncthreads();
    if (t < HDIM) g_pool[(size_t)g * HDIM + t] = 0.f;
    if (t == HDIM) g_cnt[g] = 0.f;
}

// ------------------------- launch -------------------------------------------
extern "C" void kernel_launch(void* const* d_in, const int* in_sizes, int n_in,
                              void* d_out, int out_size) {
    const float* node_feats = (const float*)d_in[0];
    const int*   edge_index = (const int*)d_in[1];
    const float* edge_feats = (const float*)d_in[2];
    const int*   graph_id   = (const int*)d_in[3];
    const float* emb_W      = (const float*)d_in[4];
    const float* emb_b      = (const float*)d_in[5];
    const float* conv_W     = (const float*)d_in[6];
    // d_in[7] = conv_b: zeros; constant bias cancels exactly in BN.
    const float* bn_gamma   = (const float*)d_in[8];
    const float* bn_beta    = (const float*)d_in[9];
    const float* fc_W       = (const float*)d_in[10];
    const float* fc_b       = (const float*)d_in[11];
    const float* out_W      = (const float*)d_in[12];
    const float* out_b      = (const float*)d_in[13];

    int nNodes  = in_sizes[0] / NODE_DIM;
    int nEdges  = in_sizes[1] / 2;
    int nConv   = in_sizes[6] / (KD * OUTC);

    int nsm = 148;
    cudaDeviceGetAttribute(&nsm, cudaDevAttrMultiProcessorCount, 0);

    size_t convSmem = (size_t)SMEM_WORDS * 4;   // 92160 B
    cudaFuncSetAttribute(conv_mma_kernel,
                         cudaFuncAttributeMaxDynamicSharedMemorySize, (int)convSmem);

    // launch 1: embedding
    emb_kernel<<<2048, 256>>>(node_feats, emb_W, emb_b, nNodes);
    // launch 2: efsplit + cursor zero + all-layer bfrag (fused)
    {
        long long tot = (long long)nEdges * 24;
        int efBlocks = (int)((tot + 255) / 256);
        int bfragTotal = nConv * BU2;
        int bfBlocks = (bfragTotal + 255) / 256;
        prep_kernel<<<efBlocks + bfBlocks, 256>>>(edge_feats, conv_W,
                                                  nEdges, nNodes, efBlocks, bfragTotal);
    }
    // launches 3-5: CSR build
    int eb = (nEdges + 255) / 256;
    hist_kernel<<<eb, 256>>>(edge_index, nEdges);
    scan_kernel<<<1, 1024>>>(nNodes, nEdges);
    scatter_kernel<<<eb, 256>>>(edge_index, nEdges);

    int nTiles = (nEdges + 127) / 128;
    float invE = 1.0f / (float)nEdges;
    int gateBlocks = (nNodes + 7) / 8;
    for (int l = 0; l < nConv; l++) {
        // launch 6 (first iteration): conv — lands on ncu's -s 5 -c 1 window
        conv_mma_kernel<<<2 * nsm, 256, convSmem>>>(edge_index, l, nEdges, nTiles);
        bn_coef_kernel<<<1, OUTC>>>(bn_gamma + l * OUTC, bn_beta + l * OUTC, invE);
        csr_gate_kernel<<<gateBlocks, 256>>>(graph_id, nNodes, l == nConv - 1);
    }

    head_kernel<<<out_size, PRED_H>>>(fc_W, fc_b, out_W, out_b, (float*)d_out);
}

// round 14
// speedup vs baseline: 1.1291x; 1.0314x over previous
#include <cuda_runtime.h>
#include <cuda_bf16.h>
#include <cuda_fp16.h>
#include <cstdint>

#define HDIM 64
#define NODE_DIM 92
#define EDGE_DIM 41
#define KD 169            // 2H + EDGE_DIM
#define OUTC 128          // 2H
#define PRED_H 128
#define BN_EPS 1e-5f
#define MAX_NODES 100000
#define MAX_EDGES 1600000
#define MAX_GRAPHS 4096
#define MAX_CONV 3

#define NCH 11            // k16 chunks (K=176 padded)
#define ASTRIDE 92        // A smem row stride (u32 words): 88 data + 4 pad
#define AWORDS (128 * ASTRIDE)               // 47104 B
#define BU2    (NCH * 16 * 32)               // 5632 uint2 = 45056 B
#define SMEM_WORDS (AWORDS + 2 * BU2)        // 92160 B -> 2 CTAs/SM

// ------------------------- device scratch ------------------------------------
__device__ float  g_h[MAX_NODES * HDIM];
__device__ __half g_zh[(size_t)MAX_EDGES * OUTC];   // CSR-permuted pre-BN activations
__device__ float  g_sum[OUTC];
__device__ float  g_sumsq[OUTC];
__device__ float  g_coef[2 * OUTC];
__device__ float  g_pool[MAX_GRAPHS * HDIM];
__device__ float  g_cnt[MAX_GRAPHS];
__device__ __align__(16) uint2    g_bfrag[MAX_CONV * BU2];
__device__ __align__(16) uint32_t g_hh[(size_t)MAX_NODES * 32];   // h as fp16x2
__device__ __align__(16) uint32_t g_efh[(size_t)MAX_EDGES * 24];  // ef as fp16x2
// CSR
__device__ int g_rowstart[MAX_NODES + 1];
__device__ int g_cursor[MAX_NODES];
__device__ int g_epos[MAX_EDGES];                   // edge -> CSR position
__device__ int g_bsum[1024];

// ------------------------- helpers ------------------------------------------
__device__ __forceinline__ float fsig(float x) {
    float t;
    asm("tanh.approx.f32 %0, %1;" : "=f"(t) : "f"(0.5f * x));
    return fmaf(0.5f, t, 0.5f);
}
__device__ __forceinline__ float fsp(float x) {
    float t = __expf(-fabsf(x));
    return fmaxf(x, 0.f) + __logf(1.f + t);
}

__device__ __forceinline__ void mma16816(float* d, const uint32_t* a, uint2 b) {
    asm volatile("mma.sync.aligned.m16n8k16.row.col.f32.f16.f16.f32 "
                 "{%0,%1,%2,%3}, {%4,%5,%6,%7}, {%8,%9}, {%0,%1,%2,%3};"
                 : "+f"(d[0]), "+f"(d[1]), "+f"(d[2]), "+f"(d[3])
                 : "r"(a[0]), "r"(a[1]), "r"(a[2]), "r"(a[3]), "r"(b.x), "r"(b.y));
}
__device__ __forceinline__ uint32_t smem_u32(const void* p) {
    uint32_t a;
    asm("{ .reg .u64 t; cvta.to.shared.u64 t, %1; cvt.u32.u64 %0, t; }" : "=r"(a) : "l"(p));
    return a;
}
__device__ __forceinline__ void cp16(uint32_t dst, const void* src, int sz) {
    asm volatile("cp.async.cg.shared.global [%0], [%1], 16, %2;"
                 :: "r"(dst), "l"(src), "r"(sz) : "memory");
}
#define CP_COMMIT() asm volatile("cp.async.commit_group;" ::: "memory")
#define CP_WAIT0()  asm volatile("cp.async.wait_group 0;" ::: "memory")
__device__ __forceinline__ void stcs32(void* p, uint32_t v) {
    asm volatile("st.global.cs.u32 [%0], %1;" :: "l"(p), "r"(v) : "memory");
}
__device__ __forceinline__ uint32_t ldcs32(const void* p) {
    uint32_t v;
    asm volatile("ld.global.cs.u32 %0, [%1];" : "=r"(v) : "l"(p));
    return v;
}

// ------------------------- 1. node embedding (writes g_h + g_hh) ------------
__global__ void __launch_bounds__(256)
emb_kernel(const float* __restrict__ nf, const float* __restrict__ Wm,
           const float* __restrict__ b, int nNodes) {
    __shared__ float sW[NODE_DIM * HDIM];
    __shared__ float sXn[8][NODE_DIM];
    for (int i = threadIdx.x; i < NODE_DIM * HDIM; i += 256) sW[i] = Wm[i];
    __syncthreads();
    int wid = threadIdx.x >> 5, lane = threadIdx.x & 31;
    int gw = (blockIdx.x * 256 + threadIdx.x) >> 5;
    int nW = (gridDim.x * 256) >> 5;
    float b0 = b[2 * lane], b1 = b[2 * lane + 1];
    for (int n = gw; n < nNodes; n += nW) {
        __syncwarp();
        for (int k = lane; k < NODE_DIM; k += 32) sXn[wid][k] = nf[(size_t)n * NODE_DIM + k];
        __syncwarp();
        float a0 = b0, a1 = b1;
        #pragma unroll 4
        for (int k = 0; k < NODE_DIM; k++) {
            float xv = sXn[wid][k];
            float2 w = ((const float2*)sW)[k * 32 + lane];
            a0 = fmaf(xv, w.x, a0);
            a1 = fmaf(xv, w.y, a1);
        }
        ((float2*)(g_h + (size_t)n * HDIM))[lane] = make_float2(a0, a1);
        __half2 h = __floats2half2_rn(a0, a1);
        g_hh[(size_t)n * 32 + lane] = *reinterpret_cast<uint32_t*>(&h);
    }
}

// ------------------------- 2. efsplit + bfrag + cursor-zero (one launch) ----
__global__ void __launch_bounds__(256)
prep_kernel(const float* __restrict__ ef, const float* __restrict__ W,
            int nEdges, int nNodes, int efBlocks, int bfragTotal) {
    if ((int)blockIdx.x >= efBlocks) {
        // ---- bfrag part ----
        int idx = (blockIdx.x - efBlocks) * 256 + threadIdx.x;
        if (idx >= bfragTotal) return;
        int l = idx / BU2, r = idx % BU2;
        int lane = r & 31;
        int nt   = (r >> 5) & 15;
        int bi   = r >> 9;
        const float* Wl = W + (size_t)l * KD * OUTC;
        int n    = nt * 8 + (lane >> 2);
        int k0   = bi * 16 + (lane & 3) * 2;
        uint32_t out[2];
        #pragma unroll
        for (int half = 0; half < 2; half++) {
            float w0 = 0.f, w1 = 0.f;
            int ka = k0 + half * 8, kb = ka + 1;
            if (ka < KD) w0 = Wl[ka * OUTC + n];
            if (kb < KD) w1 = Wl[kb * OUTC + n];
            __half2 h = __floats2half2_rn(w0, w1);
            out[half] = *reinterpret_cast<uint32_t*>(&h);
        }
        g_bfrag[idx] = make_uint2(out[0], out[1]);
        return;
    }
    // ---- efsplit part (+ cursor zero) ----
    long long idx = (long long)blockIdx.x * 256 + threadIdx.x;
    if (idx < nNodes) g_cursor[(int)idx] = 0;
    if (idx >= (long long)nEdges * 24) return;
    int w = (int)(idx % 24);
    long long e = idx / 24;
    int c = 2 * w;
    float f0 = 0.f, f1 = 0.f;
    if (c < EDGE_DIM)     f0 = ef[e * EDGE_DIM + c];
    if (c + 1 < EDGE_DIM) f1 = ef[e * EDGE_DIM + c + 1];
    __half2 h = __floats2half2_rn(f0, f1);
    g_efh[idx] = *reinterpret_cast<uint32_t*>(&h);
}

// ------------------------- CSR build -----------------------------------------
__global__ void hist_kernel(const int* __restrict__ ei, int nEdges) {
    int e = blockIdx.x * 256 + threadIdx.x;
    if (e < nEdges) atomicAdd(&g_cursor[ei[e]], 1);
}
__global__ void __launch_bounds__(1024)
scan1_kernel(int n) {
    __shared__ int wsum[32];
    int tid = threadIdx.x;
    int i = blockIdx.x * 1024 + tid;
    int c = (i < n) ? g_cursor[i] : 0;
    int v = c;
    #pragma unroll
    for (int o = 1; o < 32; o <<= 1) {
        int t = __shfl_up_sync(0xffffffffu, v, o);
        if ((tid & 31) >= o) v += t;
    }
    if ((tid & 31) == 31) wsum[tid >> 5] = v;
    __syncthreads();
    if (tid < 32) {
        int s = wsum[tid];
        #pragma unroll
        for (int o = 1; o < 32; o <<= 1) {
            int t = __shfl_up_sync(0xffffffffu, s, o);
            if (tid >= o) s += t;
        }
        wsum[tid] = s;
    }
    __syncthreads();
    int incl = v + ((tid >= 32) ? wsum[(tid >> 5) - 1] : 0);
    if (i < n) g_rowstart[i] = incl - c;
    if (tid == 1023) g_bsum[blockIdx.x] = incl;
}
__global__ void __launch_bounds__(1024)
scan2_kernel(int nb) {
    __shared__ int wsum[32];
    int tid = threadIdx.x;
    int v = (tid < nb) ? g_bsum[tid] : 0;
    #pragma unroll
    for (int o = 1; o < 32; o <<= 1) {
        int t = __shfl_up_sync(0xffffffffu, v, o);
        if ((tid & 31) >= o) v += t;
    }
    if ((tid & 31) == 31) wsum[tid >> 5] = v;
    __syncthreads();
    if (tid < 32) {
        int s = wsum[tid];
        #pragma unroll
        for (int o = 1; o < 32; o <<= 1) {
            int t = __shfl_up_sync(0xffffffffu, s, o);
            if (tid >= o) s += t;
        }
        wsum[tid] = s;
    }
    __syncthreads();
    int incl = v + ((tid >= 32) ? wsum[(tid >> 5) - 1] : 0);
    if (tid < nb) g_bsum[tid] = incl;
}
__global__ void __launch_bounds__(1024)
scan3_kernel(int n, int nEdges) {
    int i = blockIdx.x * 1024 + threadIdx.x;
    if (i >= n) return;
    int off = blockIdx.x ? g_bsum[blockIdx.x - 1] : 0;
    int ex = g_rowstart[i] + off;
    g_rowstart[i] = ex;
    g_cursor[i] = ex;
    if (i == n - 1) g_rowstart[n] = nEdges;
}
__global__ void scatter_kernel(const int* __restrict__ ei, int nEdges) {
    int e = blockIdx.x * 256 + threadIdx.x;
    if (e >= nEdges) return;
    g_epos[e] = atomicAdd(&g_cursor[ei[e]], 1);
}

// ------------------------- conv edge GEMM (2 CTAs/SM, N-split) --------------
__device__ __forceinline__ void gatherAsync(uint32_t* sA, const int* __restrict__ ei,
                                            int nEdges, int t, int nTiles) {
    if (t >= nTiles) return;
    int j = threadIdx.x;
    int row = j >> 1, half = j & 1;
    int e = (t << 7) + row;
    bool valid = e < nEdges;
    int ec = valid ? e : 0;
    int sz = valid ? 16 : 0;
    int node = ei[half ? nEdges + ec : ec];
    const char* hs = (const char*)(g_hh + (size_t)node * 32);
    uint32_t* rw = sA + row * ASTRIDE;
    uint32_t dh = smem_u32(rw + half * 32);
    #pragma unroll
    for (int i = 0; i < 8; i++) cp16(dh + i * 16, hs + i * 16, sz);
    const char* es = (const char*)(g_efh + (size_t)ec * 24 + half * 12);
    uint32_t de = smem_u32(rw + 64 + half * 12);
    #pragma unroll
    for (int i = 0; i < 3; i++) cp16(de + i * 16, es + i * 16, sz);
    CP_COMMIT();
}

__device__ __forceinline__ void kloop(float acc[2][4][4], const uint32_t* aRow0,
                                      const uint2* bBase, int nh, int q) {
    #pragma unroll 1
    for (int bi = 0; bi < NCH; bi++) {
        uint2 b[4];
        const uint2* bp = bBase + bi * 512 + nh * 128;
        #pragma unroll
        for (int n4 = 0; n4 < 4; n4++) b[n4] = bp[n4 * 32];
        uint32_t a[2][4];
        int aw = bi * 8 + q;
        #pragma unroll
        for (int mt = 0; mt < 2; mt++) {
            const uint32_t* ar = aRow0 + mt * 16 * ASTRIDE;
            a[mt][0] = ar[aw];         a[mt][1] = ar[8 * ASTRIDE + aw];
            a[mt][2] = ar[aw + 4];     a[mt][3] = ar[8 * ASTRIDE + aw + 4];
        }
        #pragma unroll
        for (int n4 = 0; n4 < 4; n4++) {
            mma16816(acc[0][n4], a[0], b[n4]);
            mma16816(acc[1][n4], a[1], b[n4]);
        }
    }
}

__device__ __forceinline__ void statsEpi(float acc[2][4][4], int nh, const int* pe,
                                         int wn, int q, float* ssum, float* ssq) {
    #pragma unroll
    for (int mt = 0; mt < 2; mt++)
        #pragma unroll
        for (int n4 = 0; n4 < 4; n4++) {
            float c0 = acc[mt][n4][0], c1 = acc[mt][n4][1];
            float c2 = acc[mt][n4][2], c3 = acc[mt][n4][3];
            int s = nh * 8 + n4 * 2;
            ssum[s]     += c0 + c2;   ssum[s + 1] += c1 + c3;
            ssq[s]      += c0 * c0 + c2 * c2;
            ssq[s + 1]  += c1 * c1 + c3 * c3;
        }
    #pragma unroll
    for (int mt = 0; mt < 2; mt++)
        #pragma unroll
        for (int hf = 0; hf < 2; hf++) {
            int p = pe[mt * 2 + hf];
            if (p >= 0) {
                __half* base = g_zh + (size_t)p * OUTC + wn * 64 + nh * 32 + 2 * q;
                #pragma unroll
                for (int n4 = 0; n4 < 4; n4++) {
                    __half2 h = __floats2half2_rn(acc[mt][n4][2 * hf],
                                                  acc[mt][n4][2 * hf + 1]);
                    stcs32(base + n4 * 8, *reinterpret_cast<uint32_t*>(&h));
                }
            }
        }
}

__global__ void __launch_bounds__(256, 2)
conv_mma_kernel(const int* __restrict__ ei, int l, int nEdges, int nTiles) {
    extern __shared__ uint32_t sm[];
    uint32_t* sA = sm;
    uint2*    sB = (uint2*)(sm + AWORDS);

    const int tid = threadIdx.x, wid = tid >> 5, lane = tid & 31;
    const int q = lane & 3, r8 = lane >> 2;
    const int wm = wid & 3, wn = wid >> 2;

    gatherAsync(sA, ei, nEdges, blockIdx.x, nTiles);
    const uint2* bf = g_bfrag + (size_t)l * BU2;
    for (int i = tid; i < BU2 / 2; i += 256)
        ((uint4*)sB)[i] = ((const uint4*)bf)[i];

    float ssum[16], ssq[16];
    #pragma unroll
    for (int j = 0; j < 16; j++) { ssum[j] = 0.f; ssq[j] = 0.f; }

    CP_WAIT0();
    __syncthreads();

    const uint32_t* aRow0 = sA + (wm * 32 + r8) * ASTRIDE;
    const uint2*    bBase = sB + (wn * 8) * 32 + lane;

    for (int t = blockIdx.x; t < nTiles; t += gridDim.x) {
        const int e0 = t << 7;
        int pe[4];
        #pragma unroll
        for (int mt = 0; mt < 2; mt++)
            #pragma unroll
            for (int hf = 0; hf < 2; hf++) {
                int e = e0 + wm * 32 + mt * 16 + hf * 8 + r8;
                pe[mt * 2 + hf] = (e < nEdges) ? __ldg(&g_epos[e]) : -1;
            }
        {   // N half 0
            float acc[2][4][4];
            #pragma unroll
            for (int mt = 0; mt < 2; mt++)
                #pragma unroll
                for (int n4 = 0; n4 < 4; n4++)
                    #pragma unroll
                    for (int jj = 0; jj < 4; jj++) acc[mt][n4][jj] = 0.f;
            kloop(acc, aRow0, bBase, 0, q);
            statsEpi(acc, 0, pe, wn, q, ssum, ssq);
        }
        {   // N half 1 (+ prefetch next tile between MMA and epilogue)
            float acc[2][4][4];
            #pragma unroll
            for (int mt = 0; mt < 2; mt++)
                #pragma unroll
                for (int n4 = 0; n4 < 4; n4++)
                    #pragma unroll
                    for (int jj = 0; jj < 4; jj++) acc[mt][n4][jj] = 0.f;
            kloop(acc, aRow0, bBase, 1, q);
            __syncthreads();
            gatherAsync(sA, ei, nEdges, t + gridDim.x, nTiles);
            statsEpi(acc, 1, pe, wn, q, ssum, ssq);
        }
        CP_WAIT0();
        __syncthreads();
    }

    #pragma unroll
    for (int j = 0; j < 16; j++) {
        #pragma unroll
        for (int ofs = 4; ofs < 32; ofs <<= 1) {
            ssum[j] += __shfl_xor_sync(0xffffffffu, ssum[j], ofs);
            ssq[j]  += __shfl_xor_sync(0xffffffffu, ssq[j], ofs);
        }
    }
    if (lane < 4) {
        #pragma unroll
        for (int nh = 0; nh < 2; nh++)
            #pragma unroll
            for (int n4 = 0; n4 < 4; n4++)
                #pragma unroll
                for (int jj = 0; jj < 2; jj++) {
                    int col = wn * 64 + nh * 32 + n4 * 8 + 2 * lane + jj;
                    atomicAdd(&g_sum[col],   ssum[nh * 8 + n4 * 2 + jj]);
                    atomicAdd(&g_sumsq[col], ssq[nh * 8 + n4 * 2 + jj]);
                }
    }
}

// ------------------------- BN coefficients (self-zeroing stats) -------------
__global__ void bn_coef_kernel(const float* __restrict__ gamma,
                               const float* __restrict__ beta, float invE) {
    int c = threadIdx.x;
    float s = g_sum[c], ss = g_sumsq[c];
    float mean = s * invE;
    float var  = fmaf(-mean, mean, ss * invE);
    float a    = gamma[c] * rsqrtf(var + BN_EPS);
    g_coef[c]        = a;
    g_coef[OUTC + c] = fmaf(-mean, a, beta[c]);
    g_sum[c] = 0.f;
    g_sumsq[c] = 0.f;
}

// ------------------------- CSR gate: streaming z (warp per node) ------------
__global__ void __launch_bounds__(256)
csr_gate_kernel(const int* __restrict__ gidArr, int nNodes, int doPool) {
    int gw = blockIdx.x * 8 + (threadIdx.x >> 5);
    if (gw >= nNodes) return;
    int lane = threadIdx.x & 31;

    float sa0 = g_coef[2 * lane],             sa1 = g_coef[2 * lane + 1];
    float ha0 = g_coef[OUTC + 2 * lane],      ha1 = g_coef[OUTC + 2 * lane + 1];
    float sb0 = g_coef[64 + 2 * lane],        sb1 = g_coef[64 + 2 * lane + 1];
    float hb0 = g_coef[OUTC + 64 + 2 * lane], hb1 = g_coef[OUTC + 64 + 2 * lane + 1];

    int beg = g_rowstart[gw], end = g_rowstart[gw + 1];
    float a0 = 0.f, a1 = 0.f;
    const uint32_t* zr = (const uint32_t*)(g_zh) + (size_t)beg * 64;
    #pragma unroll 2
    for (int i = beg; i < end; i++, zr += 64) {
        uint32_t A = ldcs32(zr + lane);
        uint32_t B = ldcs32(zr + 32 + lane);
        __half2 ha = *reinterpret_cast<__half2*>(&A);
        __half2 hb = *reinterpret_cast<__half2*>(&B);
        float na0 = fmaf(__low2float(ha),  sa0, ha0);
        float na1 = fmaf(__high2float(ha), sa1, ha1);
        float nb0 = fmaf(__low2float(hb),  sb0, hb0);
        float nb1 = fmaf(__high2float(hb), sb1, hb1);
        a0 += fsig(na0) * fsp(nb0);
        a1 += fsig(na1) * fsp(nb1);
    }
    float2* hp = (float2*)(g_h + (size_t)gw * HDIM) + lane;
    float2 hv = *hp;
    hv.x += a0; hv.y += a1;
    *hp = hv;
    __half2 hh = __floats2half2_rn(hv.x, hv.y);
    g_hh[(size_t)gw * 32 + lane] = *reinterpret_cast<uint32_t*>(&hh);
    if (doPool) {
        int g = gidArr[gw];
        float* pr = g_pool + (size_t)g * HDIM + 2 * lane;
        asm volatile("red.global.add.v2.f32 [%0], {%1, %2};"
                     :: "l"(pr), "f"(hv.x), "f"(hv.y) : "memory");
        if (lane == 0) atomicAdd(&g_cnt[g], 1.0f);
    }
}

// ------------------------- prediction head (self-zeroing pool) --------------
__global__ void __launch_bounds__(PRED_H)
head_kernel(const float* __restrict__ fcW, const float* __restrict__ fcb,
            const float* __restrict__ outW, const float* __restrict__ outb,
            float* __restrict__ out) {
    __shared__ float sp[HDIM];
    __shared__ float red[PRED_H];
    int g = blockIdx.x, t = threadIdx.x;
    if (t < HDIM) {
        float c = g_cnt[g];
        sp[t] = g_pool[(size_t)g * HDIM + t] / fmaxf(c, 1.0f);
    }
    __syncthreads();
    float acc = fcb[t];
    #pragma unroll
    for (int k = 0; k < HDIM; k++) acc = fmaf(sp[k], fcW[k * PRED_H + t], acc);
    red[t] = fmaxf(acc, 0.f) + log1pf(expf(-fabsf(acc)));
    red[t] *= outW[t];
    __syncthreads();
    for (int sft = PRED_H / 2; sft > 0; sft >>= 1) {
        if (t < sft) red[t] += red[t + sft];
        __syncthreads();
    }
    if (t == 0) out[g] = red[0] + outb[0];
    __syncthreads();
    if (t < HDIM) g_pool[(size_t)g * HDIM + t] = 0.f;
    if (t == HDIM) g_cnt[g] = 0.f;
}

// ------------------------- launch -------------------------------------------
extern "C" void kernel_launch(void* const* d_in, const int* in_sizes, int n_in,
                              void* d_out, int out_size) {
    const float* node_feats = (const float*)d_in[0];
    const int*   edge_index = (const int*)d_in[1];
    const float* edge_feats = (const float*)d_in[2];
    const int*   graph_id   = (const int*)d_in[3];
    const float* emb_W      = (const float*)d_in[4];
    const float* emb_b      = (const float*)d_in[5];
    const float* conv_W     = (const float*)d_in[6];
    // d_in[7] = conv_b: zeros; constant bias cancels exactly in BN.
    const float* bn_gamma   = (const float*)d_in[8];
    const float* bn_beta    = (const float*)d_in[9];
    const float* fc_W       = (const float*)d_in[10];
    const float* fc_b       = (const float*)d_in[11];
    const float* out_W      = (const float*)d_in[12];
    const float* out_b      = (const float*)d_in[13];

    int nNodes  = in_sizes[0] / NODE_DIM;
    int nEdges  = in_sizes[1] / 2;
    int nConv   = in_sizes[6] / (KD * OUTC);

    int nsm = 148;
    cudaDeviceGetAttribute(&nsm, cudaDevAttrMultiProcessorCount, 0);

    size_t convSmem = (size_t)SMEM_WORDS * 4;   // 92160 B
    cudaFuncSetAttribute(conv_mma_kernel,
                         cudaFuncAttributeMaxDynamicSharedMemorySize, (int)convSmem);

    emb_kernel<<<2048, 256>>>(node_feats, emb_W, emb_b, nNodes);
    {
        long long tot = (long long)nEdges * 24;
        int efBlocks = (int)((tot + 255) / 256);
        int bfragTotal = nConv * BU2;
        int bfBlocks = (bfragTotal + 255) / 256;
        prep_kernel<<<efBlocks + bfBlocks, 256>>>(edge_feats, conv_W,
                                                  nEdges, nNodes, efBlocks, bfragTotal);
    }

    // ---- CSR build (edge_index constant across layers) ----
    int eb = (nEdges + 255) / 256;
    int nb1 = (nNodes + 1023) / 1024;
    hist_kernel<<<eb, 256>>>(edge_index, nEdges);
    scan1_kernel<<<nb1, 1024>>>(nNodes);
    scan2_kernel<<<1, 1024>>>(nb1);
    scan3_kernel<<<nb1, 1024>>>(nNodes, nEdges);
    scatter_kernel<<<eb, 256>>>(edge_index, nEdges);

    int nTiles = (nEdges + 127) / 128;
    float invE = 1.0f / (float)nEdges;
    int gateBlocks = (nNodes + 7) / 8;
    for (int l = 0; l < nConv; l++) {
        conv_mma_kernel<<<2 * nsm, 256, convSmem>>>(edge_index, l, nEdges, nTiles);
        bn_coef_kernel<<<1, OUTC>>>(bn_gamma + l * OUTC, bn_beta + l * OUTC, invE);
        csr_gate_kernel<<<gateBlocks, 256>>>(graph_id, nNodes, l == nConv - 1);
    }

    head_kernel<<<out_size, PRED_H>>>(fc_W, fc_b, out_W, out_b, (float*)d_out);
}

// round 15
// speedup vs baseline: 1.1883x; 1.0524x over previous
#include <cuda_runtime.h>
#include <cuda_bf16.h>
#include <cuda_fp16.h>
#include <cstdint>

#define HDIM 64
#define NODE_DIM 92
#define EDGE_DIM 41
#define KD 169            // 2H + EDGE_DIM
#define OUTC 128          // 2H
#define PRED_H 128
#define BN_EPS 1e-5f
#define MAX_NODES 100000
#define MAX_EDGES 1600000
#define MAX_GRAPHS 4096
#define MAX_CONV 3

#define NCH 11            // k16 chunks (K=176 padded)
#define ASTRIDE 92        // A smem row stride (u32 words): 88 data + 4 pad
#define AWORDS (128 * ASTRIDE)               // 47104 B
#define BU2    (NCH * 16 * 32)               // 5632 uint2 = 45056 B
#define SMEM_WORDS (AWORDS + 2 * BU2)        // 92160 B -> 2 CTAs/SM

// ------------------------- device scratch ------------------------------------
__device__ float  g_h[MAX_NODES * HDIM];
__device__ __half g_zh[(size_t)MAX_EDGES * OUTC];   // CSR-ordered pre-BN activations
__device__ float  g_sum[OUTC];
__device__ float  g_sumsq[OUTC];
__device__ float  g_coef[2 * OUTC];
__device__ float  g_pool[MAX_GRAPHS * HDIM];
__device__ float  g_cnt[MAX_GRAPHS];
__device__ __align__(16) uint2    g_bfrag[MAX_CONV * BU2];
__device__ __align__(16) uint32_t g_hh[(size_t)MAX_NODES * 32];   // h as fp16x2
__device__ __align__(16) uint32_t g_efh[(size_t)MAX_EDGES * 24];  // ef fp16x2, CSR order
// CSR
__device__ int  g_rowstart[MAX_NODES + 1];
__device__ int  g_cursor[MAX_NODES];
__device__ int  g_epos[MAX_EDGES];                  // edge -> CSR position
__device__ int2 g_ecsr[MAX_EDGES];                  // CSR position -> (src, dst)
__device__ int  g_bsum[1024];

// ------------------------- helpers ------------------------------------------
__device__ __forceinline__ float fsig(float x) {
    float t;
    asm("tanh.approx.f32 %0, %1;" : "=f"(t) : "f"(0.5f * x));
    return fmaf(0.5f, t, 0.5f);
}
__device__ __forceinline__ float fsp(float x) {
    float t = __expf(-fabsf(x));
    return fmaxf(x, 0.f) + __logf(1.f + t);
}

__device__ __forceinline__ void mma16816(float* d, const uint32_t* a, uint2 b) {
    asm volatile("mma.sync.aligned.m16n8k16.row.col.f32.f16.f16.f32 "
                 "{%0,%1,%2,%3}, {%4,%5,%6,%7}, {%8,%9}, {%0,%1,%2,%3};"
                 : "+f"(d[0]), "+f"(d[1]), "+f"(d[2]), "+f"(d[3])
                 : "r"(a[0]), "r"(a[1]), "r"(a[2]), "r"(a[3]), "r"(b.x), "r"(b.y));
}
__device__ __forceinline__ void ldsm4(uint32_t* a, uint32_t addr) {
    asm volatile("ldmatrix.sync.aligned.m8n8.x4.shared.b16 {%0,%1,%2,%3}, [%4];"
                 : "=r"(a[0]), "=r"(a[1]), "=r"(a[2]), "=r"(a[3]) : "r"(addr));
}
__device__ __forceinline__ uint32_t smem_u32(const void* p) {
    uint32_t a;
    asm("{ .reg .u64 t; cvta.to.shared.u64 t, %1; cvt.u32.u64 %0, t; }" : "=r"(a) : "l"(p));
    return a;
}
__device__ __forceinline__ void cp16(uint32_t dst, const void* src, int sz) {
    asm volatile("cp.async.cg.shared.global [%0], [%1], 16, %2;"
                 :: "r"(dst), "l"(src), "r"(sz) : "memory");
}
#define CP_COMMIT() asm volatile("cp.async.commit_group;" ::: "memory")
#define CP_WAIT0()  asm volatile("cp.async.wait_group 0;" ::: "memory")
__device__ __forceinline__ void stcs32(void* p, uint32_t v) {
    asm volatile("st.global.cs.u32 [%0], %1;" :: "l"(p), "r"(v) : "memory");
}
__device__ __forceinline__ uint32_t ldcs32(const void* p) {
    uint32_t v;
    asm volatile("ld.global.cs.u32 %0, [%1];" : "=r"(v) : "l"(p));
    return v;
}

// ------------------------- 1. node embedding (+ cursor zero) ----------------
__global__ void __launch_bounds__(256)
emb_kernel(const float* __restrict__ nf, const float* __restrict__ Wm,
           const float* __restrict__ b, int nNodes) {
    {
        int gi = blockIdx.x * 256 + threadIdx.x;
        if (gi < nNodes) g_cursor[gi] = 0;
    }
    __shared__ float sW[NODE_DIM * HDIM];
    __shared__ float sXn[8][NODE_DIM];
    for (int i = threadIdx.x; i < NODE_DIM * HDIM; i += 256) sW[i] = Wm[i];
    __syncthreads();
    int wid = threadIdx.x >> 5, lane = threadIdx.x & 31;
    int gw = (blockIdx.x * 256 + threadIdx.x) >> 5;
    int nW = (gridDim.x * 256) >> 5;
    float b0 = b[2 * lane], b1 = b[2 * lane + 1];
    for (int n = gw; n < nNodes; n += nW) {
        __syncwarp();
        for (int k = lane; k < NODE_DIM; k += 32) sXn[wid][k] = nf[(size_t)n * NODE_DIM + k];
        __syncwarp();
        float a0 = b0, a1 = b1;
        #pragma unroll 4
        for (int k = 0; k < NODE_DIM; k++) {
            float xv = sXn[wid][k];
            float2 w = ((const float2*)sW)[k * 32 + lane];
            a0 = fmaf(xv, w.x, a0);
            a1 = fmaf(xv, w.y, a1);
        }
        ((float2*)(g_h + (size_t)n * HDIM))[lane] = make_float2(a0, a1);
        __half2 h = __floats2half2_rn(a0, a1);
        g_hh[(size_t)n * 32 + lane] = *reinterpret_cast<uint32_t*>(&h);
    }
}

// ------------------------- CSR build -----------------------------------------
__global__ void hist_kernel(const int* __restrict__ ei, int nEdges) {
    int e = blockIdx.x * 256 + threadIdx.x;
    if (e < nEdges) atomicAdd(&g_cursor[ei[e]], 1);
}
__global__ void __launch_bounds__(1024)
scan1_kernel(int n) {
    __shared__ int wsum[32];
    int tid = threadIdx.x;
    int i = blockIdx.x * 1024 + tid;
    int c = (i < n) ? g_cursor[i] : 0;
    int v = c;
    #pragma unroll
    for (int o = 1; o < 32; o <<= 1) {
        int t = __shfl_up_sync(0xffffffffu, v, o);
        if ((tid & 31) >= o) v += t;
    }
    if ((tid & 31) == 31) wsum[tid >> 5] = v;
    __syncthreads();
    if (tid < 32) {
        int s = wsum[tid];
        #pragma unroll
        for (int o = 1; o < 32; o <<= 1) {
            int t = __shfl_up_sync(0xffffffffu, s, o);
            if (tid >= o) s += t;
        }
        wsum[tid] = s;
    }
    __syncthreads();
    int incl = v + ((tid >= 32) ? wsum[(tid >> 5) - 1] : 0);
    if (i < n) g_rowstart[i] = incl - c;
    if (tid == 1023) g_bsum[blockIdx.x] = incl;
}
__global__ void __launch_bounds__(1024)
scan2_kernel(int nb) {
    __shared__ int wsum[32];
    int tid = threadIdx.x;
    int v = (tid < nb) ? g_bsum[tid] : 0;
    #pragma unroll
    for (int o = 1; o < 32; o <<= 1) {
        int t = __shfl_up_sync(0xffffffffu, v, o);
        if ((tid & 31) >= o) v += t;
    }
    if ((tid & 31) == 31) wsum[tid >> 5] = v;
    __syncthreads();
    if (tid < 32) {
        int s = wsum[tid];
        #pragma unroll
        for (int o = 1; o < 32; o <<= 1) {
            int t = __shfl_up_sync(0xffffffffu, s, o);
            if (tid >= o) s += t;
        }
        wsum[tid] = s;
    }
    __syncthreads();
    int incl = v + ((tid >= 32) ? wsum[(tid >> 5) - 1] : 0);
    if (tid < nb) g_bsum[tid] = incl;
}
__global__ void __launch_bounds__(1024)
scan3_kernel(int n, int nEdges) {
    int i = blockIdx.x * 1024 + threadIdx.x;
    if (i >= n) return;
    int off = blockIdx.x ? g_bsum[blockIdx.x - 1] : 0;
    int ex = g_rowstart[i] + off;
    g_rowstart[i] = ex;
    g_cursor[i] = ex;
    if (i == n - 1) g_rowstart[n] = nEdges;
}
__global__ void scatter_kernel(const int* __restrict__ ei, int nEdges) {
    int e = blockIdx.x * 256 + threadIdx.x;
    if (e >= nEdges) return;
    int s = ei[e], d = ei[nEdges + e];
    int p = atomicAdd(&g_cursor[s], 1);
    g_epos[e] = p;
    g_ecsr[p] = make_int2(s, d);
}

// ------------------------- prep: efsplit (CSR order) + bfrag ----------------
__global__ void __launch_bounds__(256)
prep_kernel(const float* __restrict__ ef, const float* __restrict__ W,
            int nEdges, int efBlocks, int bfragTotal) {
    if ((int)blockIdx.x >= efBlocks) {
        int idx = (blockIdx.x - efBlocks) * 256 + threadIdx.x;
        if (idx >= bfragTotal) return;
        int l = idx / BU2, r = idx % BU2;
        int lane = r & 31;
        int nt   = (r >> 5) & 15;
        int bi   = r >> 9;
        const float* Wl = W + (size_t)l * KD * OUTC;
        int n    = nt * 8 + (lane >> 2);
        int k0   = bi * 16 + (lane & 3) * 2;
        uint32_t out[2];
        #pragma unroll
        for (int half = 0; half < 2; half++) {
            float w0 = 0.f, w1 = 0.f;
            int ka = k0 + half * 8, kb = ka + 1;
            if (ka < KD) w0 = Wl[ka * OUTC + n];
            if (kb < KD) w1 = Wl[kb * OUTC + n];
            __half2 h = __floats2half2_rn(w0, w1);
            out[half] = *reinterpret_cast<uint32_t*>(&h);
        }
        g_bfrag[idx] = make_uint2(out[0], out[1]);
        return;
    }
    long long idx = (long long)blockIdx.x * 256 + threadIdx.x;
    if (idx >= (long long)nEdges * 24) return;
    int w = (int)(idx % 24);
    long long e = idx / 24;
    int c = 2 * w;
    float f0 = 0.f, f1 = 0.f;
    if (c < EDGE_DIM)     f0 = ef[e * EDGE_DIM + c];
    if (c + 1 < EDGE_DIM) f1 = ef[e * EDGE_DIM + c + 1];
    __half2 h = __floats2half2_rn(f0, f1);
    int p = g_epos[e];
    g_efh[(size_t)p * 24 + w] = *reinterpret_cast<uint32_t*>(&h);
}

// ------------------------- conv edge GEMM (CSR-ordered tiles) ---------------
__device__ __forceinline__ void gatherAsync(uint32_t* sA, int nEdges, int t, int nTiles) {
    if (t >= nTiles) return;
    int j = threadIdx.x;
    int row = j >> 1, half = j & 1;
    int pos = (t << 7) + row;
    bool valid = pos < nEdges;
    int pc = valid ? pos : 0;
    int sz = valid ? 16 : 0;
    int2 nd = g_ecsr[pc];
    int node = half ? nd.y : nd.x;
    const char* hs = (const char*)(g_hh + (size_t)node * 32);
    uint32_t* rw = sA + row * ASTRIDE;
    uint32_t dh = smem_u32(rw + half * 32);
    #pragma unroll
    for (int i = 0; i < 8; i++) cp16(dh + i * 16, hs + i * 16, sz);
    const char* es = (const char*)(g_efh + (size_t)pc * 24 + half * 12);
    uint32_t de = smem_u32(rw + 64 + half * 12);
    #pragma unroll
    for (int i = 0; i < 3; i++) cp16(de + i * 16, es + i * 16, sz);
    CP_COMMIT();
}

__device__ __forceinline__ void kloop(float acc[2][4][4], uint32_t aAddr0,
                                      uint32_t aAddr1, const uint2* bBase, int nh) {
    #pragma unroll 1
    for (int bi = 0; bi < NCH; bi++) {
        uint2 b[4];
        const uint2* bp = bBase + bi * 512 + nh * 128;
        #pragma unroll
        for (int n4 = 0; n4 < 4; n4++) b[n4] = bp[n4 * 32];
        uint32_t a0[4], a1[4];
        ldsm4(a0, aAddr0 + bi * 32);
        ldsm4(a1, aAddr1 + bi * 32);
        #pragma unroll
        for (int n4 = 0; n4 < 4; n4++) {
            mma16816(acc[0][n4], a0, b[n4]);
            mma16816(acc[1][n4], a1, b[n4]);
        }
    }
}

__device__ __forceinline__ void statsEpi(float acc[2][4][4], int nh, int e0, int nEdges,
                                         int wm, int wn, int q, int r8,
                                         float* ssum, float* ssq) {
    #pragma unroll
    for (int mt = 0; mt < 2; mt++)
        #pragma unroll
        for (int n4 = 0; n4 < 4; n4++) {
            float c0 = acc[mt][n4][0], c1 = acc[mt][n4][1];
            float c2 = acc[mt][n4][2], c3 = acc[mt][n4][3];
            int s = nh * 8 + n4 * 2;
            ssum[s]     += c0 + c2;   ssum[s + 1] += c1 + c3;
            ssq[s]      += c0 * c0 + c2 * c2;
            ssq[s + 1]  += c1 * c1 + c3 * c3;
        }
    #pragma unroll
    for (int mt = 0; mt < 2; mt++)
        #pragma unroll
        for (int hf = 0; hf < 2; hf++) {
            int p = e0 + wm * 32 + mt * 16 + hf * 8 + r8;
            if (p < nEdges) {
                __half* base = g_zh + (size_t)p * OUTC + wn * 64 + nh * 32 + 2 * q;
                #pragma unroll
                for (int n4 = 0; n4 < 4; n4++) {
                    __half2 h = __floats2half2_rn(acc[mt][n4][2 * hf],
                                                  acc[mt][n4][2 * hf + 1]);
                    stcs32(base + n4 * 8, *reinterpret_cast<uint32_t*>(&h));
                }
            }
        }
}

__global__ void __launch_bounds__(256, 2)
conv_mma_kernel(int l, int nEdges, int nTiles) {
    extern __shared__ uint32_t sm[];
    uint32_t* sA = sm;
    uint2*    sB = (uint2*)(sm + AWORDS);

    const int tid = threadIdx.x, wid = tid >> 5, lane = tid & 31;
    const int q = lane & 3, r8 = lane >> 2;
    const int wm = wid & 3, wn = wid >> 2;

    gatherAsync(sA, nEdges, blockIdx.x, nTiles);
    const uint2* bf = g_bfrag + (size_t)l * BU2;
    for (int i = tid; i < BU2 / 2; i += 256)
        ((uint4*)sB)[i] = ((const uint4*)bf)[i];

    float ssum[16], ssq[16];
    #pragma unroll
    for (int j = 0; j < 16; j++) { ssum[j] = 0.f; ssq[j] = 0.f; }

    CP_WAIT0();
    __syncthreads();

    // ldmatrix base addresses per mt block (rows wm*32 + mt*16 + 0..15)
    const uint32_t sAb = smem_u32(sA);
    const uint32_t aAddr0 = sAb + (uint32_t)((wm * 32 + (lane & 15)) * (ASTRIDE * 4)) +
                            ((lane >> 4) << 4);
    const uint32_t aAddr1 = aAddr0 + 16 * (ASTRIDE * 4);
    const uint2* bBase = sB + (wn * 8) * 32 + lane;

    for (int t = blockIdx.x; t < nTiles; t += gridDim.x) {
        const int e0 = t << 7;
        {   // N half 0
            float acc[2][4][4];
            #pragma unroll
            for (int mt = 0; mt < 2; mt++)
                #pragma unroll
                for (int n4 = 0; n4 < 4; n4++)
                    #pragma unroll
                    for (int jj = 0; jj < 4; jj++) acc[mt][n4][jj] = 0.f;
            kloop(acc, aAddr0, aAddr1, bBase, 0);
            statsEpi(acc, 0, e0, nEdges, wm, wn, q, r8, ssum, ssq);
        }
        {   // N half 1 (+ prefetch next tile between MMA and epilogue)
            float acc[2][4][4];
            #pragma unroll
            for (int mt = 0; mt < 2; mt++)
                #pragma unroll
                for (int n4 = 0; n4 < 4; n4++)
                    #pragma unroll
                    for (int jj = 0; jj < 4; jj++) acc[mt][n4][jj] = 0.f;
            kloop(acc, aAddr0, aAddr1, bBase, 1);
            __syncthreads();
            gatherAsync(sA, nEdges, t + gridDim.x, nTiles);
            statsEpi(acc, 1, e0, nEdges, wm, wn, q, r8, ssum, ssq);
        }
        CP_WAIT0();
        __syncthreads();
    }

    #pragma unroll
    for (int j = 0; j < 16; j++) {
        #pragma unroll
        for (int ofs = 4; ofs < 32; ofs <<= 1) {
            ssum[j] += __shfl_xor_sync(0xffffffffu, ssum[j], ofs);
            ssq[j]  += __shfl_xor_sync(0xffffffffu, ssq[j], ofs);
        }
    }
    if (lane < 4) {
        #pragma unroll
        for (int nh = 0; nh < 2; nh++)
            #pragma unroll
            for (int n4 = 0; n4 < 4; n4++)
                #pragma unroll
                for (int jj = 0; jj < 2; jj++) {
                    int col = wn * 64 + nh * 32 + n4 * 8 + 2 * lane + jj;
                    atomicAdd(&g_sum[col],   ssum[nh * 8 + n4 * 2 + jj]);
                    atomicAdd(&g_sumsq[col], ssq[nh * 8 + n4 * 2 + jj]);
                }
    }
}

// ------------------------- BN coefficients (self-zeroing stats) -------------
__global__ void bn_coef_kernel(const float* __restrict__ gamma,
                               const float* __restrict__ beta, float invE) {
    int c = threadIdx.x;
    float s = g_sum[c], ss = g_sumsq[c];
    float mean = s * invE;
    float var  = fmaf(-mean, mean, ss * invE);
    float a    = gamma[c] * rsqrtf(var + BN_EPS);
    g_coef[c]        = a;
    g_coef[OUTC + c] = fmaf(-mean, a, beta[c]);
    g_sum[c] = 0.f;
    g_sumsq[c] = 0.f;
}

// ------------------------- CSR gate: streaming z (warp per node) ------------
__global__ void __launch_bounds__(256)
csr_gate_kernel(const int* __restrict__ gidArr, int nNodes, int doPool) {
    int gw = blockIdx.x * 8 + (threadIdx.x >> 5);
    if (gw >= nNodes) return;
    int lane = threadIdx.x & 31;

    float sa0 = g_coef[2 * lane],             sa1 = g_coef[2 * lane + 1];
    float ha0 = g_coef[OUTC + 2 * lane],      ha1 = g_coef[OUTC + 2 * lane + 1];
    float sb0 = g_coef[64 + 2 * lane],        sb1 = g_coef[64 + 2 * lane + 1];
    float hb0 = g_coef[OUTC + 64 + 2 * lane], hb1 = g_coef[OUTC + 64 + 2 * lane + 1];

    int beg = g_rowstart[gw], end = g_rowstart[gw + 1];
    float a0 = 0.f, a1 = 0.f;
    const uint32_t* zr = (const uint32_t*)(g_zh) + (size_t)beg * 64;
    #pragma unroll 2
    for (int i = beg; i < end; i++, zr += 64) {
        uint32_t A = ldcs32(zr + lane);
        uint32_t B = ldcs32(zr + 32 + lane);
        __half2 ha = *reinterpret_cast<__half2*>(&A);
        __half2 hb = *reinterpret_cast<__half2*>(&B);
        float na0 = fmaf(__low2float(ha),  sa0, ha0);
        float na1 = fmaf(__high2float(ha), sa1, ha1);
        float nb0 = fmaf(__low2float(hb),  sb0, hb0);
        float nb1 = fmaf(__high2float(hb), sb1, hb1);
        a0 += fsig(na0) * fsp(nb0);
        a1 += fsig(na1) * fsp(nb1);
    }
    float2* hp = (float2*)(g_h + (size_t)gw * HDIM) + lane;
    float2 hv = *hp;
    hv.x += a0; hv.y += a1;
    *hp = hv;
    __half2 hh = __floats2half2_rn(hv.x, hv.y);
    g_hh[(size_t)gw * 32 + lane] = *reinterpret_cast<uint32_t*>(&hh);
    if (doPool) {
        int g = gidArr[gw];
        float* pr = g_pool + (size_t)g * HDIM + 2 * lane;
        asm volatile("red.global.add.v2.f32 [%0], {%1, %2};"
                     :: "l"(pr), "f"(hv.x), "f"(hv.y) : "memory");
        if (lane == 0) atomicAdd(&g_cnt[g], 1.0f);
    }
}

// ------------------------- prediction head (self-zeroing pool) --------------
__global__ void __launch_bounds__(PRED_H)
head_kernel(const float* __restrict__ fcW, const float* __restrict__ fcb,
            const float* __restrict__ outW, const float* __restrict__ outb,
            float* __restrict__ out) {
    __shared__ float sp[HDIM];
    __shared__ float red[PRED_H];
    int g = blockIdx.x, t = threadIdx.x;
    if (t < HDIM) {
        float c = g_cnt[g];
        sp[t] = g_pool[(size_t)g * HDIM + t] / fmaxf(c, 1.0f);
    }
    __syncthreads();
    float acc = fcb[t];
    #pragma unroll
    for (int k = 0; k < HDIM; k++) acc = fmaf(sp[k], fcW[k * PRED_H + t], acc);
    red[t] = fmaxf(acc, 0.f) + log1pf(expf(-fabsf(acc)));
    red[t] *= outW[t];
    __syncthreads();
    for (int sft = PRED_H / 2; sft > 0; sft >>= 1) {
        if (t < sft) red[t] += red[t + sft];
        __syncthreads();
    }
    if (t == 0) out[g] = red[0] + outb[0];
    __syncthreads();
    if (t < HDIM) g_pool[(size_t)g * HDIM + t] = 0.f;
    if (t == HDIM) g_cnt[g] = 0.f;
}

// ------------------------- launch -------------------------------------------
extern "C" void kernel_launch(void* const* d_in, const int* in_sizes, int n_in,
                              void* d_out, int out_size) {
    const float* node_feats = (const float*)d_in[0];
    const int*   edge_index = (const int*)d_in[1];
    const float* edge_feats = (const float*)d_in[2];
    const int*   graph_id   = (const int*)d_in[3];
    const float* emb_W      = (const float*)d_in[4];
    const float* emb_b      = (const float*)d_in[5];
    const float* conv_W     = (const float*)d_in[6];
    // d_in[7] = conv_b: zeros; constant bias cancels exactly in BN.
    const float* bn_gamma   = (const float*)d_in[8];
    const float* bn_beta    = (const float*)d_in[9];
    const float* fc_W       = (const float*)d_in[10];
    const float* fc_b       = (const float*)d_in[11];
    const float* out_W      = (const float*)d_in[12];
    const float* out_b      = (const float*)d_in[13];

    int nNodes  = in_sizes[0] / NODE_DIM;
    int nEdges  = in_sizes[1] / 2;
    int nConv   = in_sizes[6] / (KD * OUTC);

    int nsm = 148;
    cudaDeviceGetAttribute(&nsm, cudaDevAttrMultiProcessorCount, 0);

    size_t convSmem = (size_t)SMEM_WORDS * 4;   // 92160 B
    cudaFuncSetAttribute(conv_mma_kernel,
                         cudaFuncAttributeMaxDynamicSharedMemorySize, (int)convSmem);

    // emb also zeroes the CSR cursor
    emb_kernel<<<2048, 256>>>(node_feats, emb_W, emb_b, nNodes);

    // ---- CSR build (edge_index constant across layers) ----
    int eb = (nEdges + 255) / 256;
    int nb1 = (nNodes + 1023) / 1024;
    hist_kernel<<<eb, 256>>>(edge_index, nEdges);
    scan1_kernel<<<nb1, 1024>>>(nNodes);
    scan2_kernel<<<1, 1024>>>(nb1);
    scan3_kernel<<<nb1, 1024>>>(nNodes, nEdges);
    scatter_kernel<<<eb, 256>>>(edge_index, nEdges);

    // ---- efsplit (CSR-permuted) + all-layer bfrag (fused) ----
    {
        long long tot = (long long)nEdges * 24;
        int efBlocks = (int)((tot + 255) / 256);
        int bfragTotal = nConv * BU2;
        int bfBlocks = (bfragTotal + 255) / 256;
        prep_kernel<<<efBlocks + bfBlocks, 256>>>(edge_feats, conv_W,
                                                  nEdges, efBlocks, bfragTotal);
    }

    int nTiles = (nEdges + 127) / 128;
    float invE = 1.0f / (float)nEdges;
    int gateBlocks = (nNodes + 7) / 8;
    for (int l = 0; l < nConv; l++) {
        conv_mma_kernel<<<2 * nsm, 256, convSmem>>>(l, nEdges, nTiles);
        bn_coef_kernel<<<1, OUTC>>>(bn_gamma + l * OUTC, bn_beta + l * OUTC, invE);
        csr_gate_kernel<<<gateBlocks, 256>>>(graph_id, nNodes, l == nConv - 1);
    }

    head_kernel<<<out_size, PRED_H>>>(fc_W, fc_b, out_W, out_b, (float*)d_out);
}

// round 16
// speedup vs baseline: 1.2060x; 1.0149x over previous
#include <cuda_runtime.h>
#include <cuda_bf16.h>
#include <cuda_fp16.h>
#include <cstdint>

#define HDIM 64
#define NODE_DIM 92
#define EDGE_DIM 41
#define KD 169            // 2H + EDGE_DIM
#define OUTC 128          // 2H
#define PRED_H 128
#define BN_EPS 1e-5f
#define MAX_NODES 100000
#define MAX_EDGES 1600000
#define MAX_GRAPHS 4096
#define MAX_CONV 3
#define EMB_BLOCKS 2048

#define NCH 11            // k16 chunks (K=176 padded)
#define ASTRIDE 92        // A smem row stride (u32 words): 88 data + 4 pad
#define AWORDS (128 * ASTRIDE)               // 47104 B
#define BU2    (NCH * 16 * 32)               // 5632 uint2 = 45056 B
#define SMEM_WORDS (AWORDS + 2 * BU2)        // 92160 B -> 2 CTAs/SM

// ------------------------- device scratch ------------------------------------
__device__ float  g_h[MAX_NODES * HDIM];
__device__ __half g_zh[(size_t)MAX_EDGES * OUTC];   // CSR-ordered pre-BN activations
__device__ float  g_sumL[MAX_CONV][OUTC];           // per-layer BN stats (self-zeroed in head)
__device__ float  g_sqL[MAX_CONV][OUTC];
__device__ float  g_pool[MAX_GRAPHS * HDIM];
__device__ float  g_cnt[MAX_GRAPHS];
__device__ __align__(16) uint2    g_bfrag[MAX_CONV * BU2];
__device__ __align__(16) uint32_t g_hh[(size_t)MAX_NODES * 32];   // h as fp16x2
__device__ __align__(16) uint32_t g_efh[(size_t)MAX_EDGES * 24];  // ef fp16x2, CSR order
// CSR
__device__ int  g_rowstart[MAX_NODES + 1];
__device__ int  g_cursor[MAX_NODES];
__device__ int  g_epos[MAX_EDGES];                  // edge -> CSR position
__device__ int2 g_ecsr[MAX_EDGES];                  // CSR position -> (src, dst)
__device__ int  g_bsum[1024];

// ------------------------- helpers ------------------------------------------
__device__ __forceinline__ float fsig(float x) {
    float t;
    asm("tanh.approx.f32 %0, %1;" : "=f"(t) : "f"(0.5f * x));
    return fmaf(0.5f, t, 0.5f);
}
__device__ __forceinline__ float fsp(float x) {
    float t = __expf(-fabsf(x));
    return fmaxf(x, 0.f) + __logf(1.f + t);
}

__device__ __forceinline__ void mma16816(float* d, const uint32_t* a, uint2 b) {
    asm volatile("mma.sync.aligned.m16n8k16.row.col.f32.f16.f16.f32 "
                 "{%0,%1,%2,%3}, {%4,%5,%6,%7}, {%8,%9}, {%0,%1,%2,%3};"
                 : "+f"(d[0]), "+f"(d[1]), "+f"(d[2]), "+f"(d[3])
                 : "r"(a[0]), "r"(a[1]), "r"(a[2]), "r"(a[3]), "r"(b.x), "r"(b.y));
}
__device__ __forceinline__ void ldsm4(uint32_t* a, uint32_t addr) {
    asm volatile("ldmatrix.sync.aligned.m8n8.x4.shared.b16 {%0,%1,%2,%3}, [%4];"
                 : "=r"(a[0]), "=r"(a[1]), "=r"(a[2]), "=r"(a[3]) : "r"(addr));
}
__device__ __forceinline__ uint32_t smem_u32(const void* p) {
    uint32_t a;
    asm("{ .reg .u64 t; cvta.to.shared.u64 t, %1; cvt.u32.u64 %0, t; }" : "=r"(a) : "l"(p));
    return a;
}
__device__ __forceinline__ void cp16(uint32_t dst, const void* src, int sz) {
    asm volatile("cp.async.cg.shared.global [%0], [%1], 16, %2;"
                 :: "r"(dst), "l"(src), "r"(sz) : "memory");
}
#define CP_COMMIT() asm volatile("cp.async.commit_group;" ::: "memory")
#define CP_WAIT0()  asm volatile("cp.async.wait_group 0;" ::: "memory")
__device__ __forceinline__ void stcs32(void* p, uint32_t v) {
    asm volatile("st.global.cs.u32 [%0], %1;" :: "l"(p), "r"(v) : "memory");
}
__device__ __forceinline__ uint32_t ldcs32(const void* p) {
    uint32_t v;
    asm volatile("ld.global.cs.u32 %0, [%1];" : "=r"(v) : "l"(p));
    return v;
}

// ------------------------- 1. fused embedding + edge histogram --------------
// blocks [0, EMB_BLOCKS): node embedding; blocks [EMB_BLOCKS, ...): histogram.
// g_cursor was zeroed by prep_kernel of the previous call (static init for call 1).
__global__ void __launch_bounds__(256)
emb_hist_kernel(const float* __restrict__ nf, const float* __restrict__ Wm,
                const float* __restrict__ b, const int* __restrict__ ei,
                int nNodes, int nEdges) {
    if ((int)blockIdx.x >= EMB_BLOCKS) {
        int e = (blockIdx.x - EMB_BLOCKS) * 256 + threadIdx.x;
        if (e < nEdges) atomicAdd(&g_cursor[ei[e]], 1);
        return;
    }
    __shared__ float sW[NODE_DIM * HDIM];
    __shared__ float sXn[8][NODE_DIM];
    for (int i = threadIdx.x; i < NODE_DIM * HDIM; i += 256) sW[i] = Wm[i];
    __syncthreads();
    int wid = threadIdx.x >> 5, lane = threadIdx.x & 31;
    int gw = (blockIdx.x * 256 + threadIdx.x) >> 5;
    int nW = (EMB_BLOCKS * 256) >> 5;
    float b0 = b[2 * lane], b1 = b[2 * lane + 1];
    for (int n = gw; n < nNodes; n += nW) {
        __syncwarp();
        for (int k = lane; k < NODE_DIM; k += 32) sXn[wid][k] = nf[(size_t)n * NODE_DIM + k];
        __syncwarp();
        float a0 = b0, a1 = b1;
        #pragma unroll 4
        for (int k = 0; k < NODE_DIM; k++) {
            float xv = sXn[wid][k];
            float2 w = ((const float2*)sW)[k * 32 + lane];
            a0 = fmaf(xv, w.x, a0);
            a1 = fmaf(xv, w.y, a1);
        }
        ((float2*)(g_h + (size_t)n * HDIM))[lane] = make_float2(a0, a1);
        __half2 h = __floats2half2_rn(a0, a1);
        g_hh[(size_t)n * 32 + lane] = *reinterpret_cast<uint32_t*>(&h);
    }
}

// ------------------------- CSR scan + scatter --------------------------------
__global__ void __launch_bounds__(1024)
scan1_kernel(int n) {
    __shared__ int wsum[32];
    int tid = threadIdx.x;
    int i = blockIdx.x * 1024 + tid;
    int c = (i < n) ? g_cursor[i] : 0;
    int v = c;
    #pragma unroll
    for (int o = 1; o < 32; o <<= 1) {
        int t = __shfl_up_sync(0xffffffffu, v, o);
        if ((tid & 31) >= o) v += t;
    }
    if ((tid & 31) == 31) wsum[tid >> 5] = v;
    __syncthreads();
    if (tid < 32) {
        int s = wsum[tid];
        #pragma unroll
        for (int o = 1; o < 32; o <<= 1) {
            int t = __shfl_up_sync(0xffffffffu, s, o);
            if (tid >= o) s += t;
        }
        wsum[tid] = s;
    }
    __syncthreads();
    int incl = v + ((tid >= 32) ? wsum[(tid >> 5) - 1] : 0);
    if (i < n) g_rowstart[i] = incl - c;
    if (tid == 1023) g_bsum[blockIdx.x] = incl;
}
__global__ void __launch_bounds__(1024)
scan2_kernel(int nb) {
    __shared__ int wsum[32];
    int tid = threadIdx.x;
    int v = (tid < nb) ? g_bsum[tid] : 0;
    #pragma unroll
    for (int o = 1; o < 32; o <<= 1) {
        int t = __shfl_up_sync(0xffffffffu, v, o);
        if ((tid & 31) >= o) v += t;
    }
    if ((tid & 31) == 31) wsum[tid >> 5] = v;
    __syncthreads();
    if (tid < 32) {
        int s = wsum[tid];
        #pragma unroll
        for (int o = 1; o < 32; o <<= 1) {
            int t = __shfl_up_sync(0xffffffffu, s, o);
            if (tid >= o) s += t;
        }
        wsum[tid] = s;
    }
    __syncthreads();
    int incl = v + ((tid >= 32) ? wsum[(tid >> 5) - 1] : 0);
    if (tid < nb) g_bsum[tid] = incl;
}
__global__ void __launch_bounds__(1024)
scan3_kernel(int n, int nEdges) {
    int i = blockIdx.x * 1024 + threadIdx.x;
    if (i >= n) return;
    int off = blockIdx.x ? g_bsum[blockIdx.x - 1] : 0;
    int ex = g_rowstart[i] + off;
    g_rowstart[i] = ex;
    g_cursor[i] = ex;
    if (i == n - 1) g_rowstart[n] = nEdges;
}
__global__ void scatter_kernel(const int* __restrict__ ei, int nEdges) {
    int e = blockIdx.x * 256 + threadIdx.x;
    if (e >= nEdges) return;
    int s = ei[e], d = ei[nEdges + e];
    int p = atomicAdd(&g_cursor[s], 1);
    g_epos[e] = p;
    g_ecsr[p] = make_int2(s, d);
}

// ------------------------- prep: efsplit (CSR) + bfrag + cursor re-zero -----
__global__ void __launch_bounds__(256)
prep_kernel(const float* __restrict__ ef, const float* __restrict__ W,
            int nEdges, int nNodes, int efBlocks, int bfragTotal) {
    if ((int)blockIdx.x >= efBlocks) {
        int idx = (blockIdx.x - efBlocks) * 256 + threadIdx.x;
        if (idx >= bfragTotal) return;
        int l = idx / BU2, r = idx % BU2;
        int lane = r & 31;
        int nt   = (r >> 5) & 15;
        int bi   = r >> 9;
        const float* Wl = W + (size_t)l * KD * OUTC;
        int n    = nt * 8 + (lane >> 2);
        int k0   = bi * 16 + (lane & 3) * 2;
        uint32_t out[2];
        #pragma unroll
        for (int half = 0; half < 2; half++) {
            float w0 = 0.f, w1 = 0.f;
            int ka = k0 + half * 8, kb = ka + 1;
            if (ka < KD) w0 = Wl[ka * OUTC + n];
            if (kb < KD) w1 = Wl[kb * OUTC + n];
            __half2 h = __floats2half2_rn(w0, w1);
            out[half] = *reinterpret_cast<uint32_t*>(&h);
        }
        g_bfrag[idx] = make_uint2(out[0], out[1]);
        return;
    }
    long long idx = (long long)blockIdx.x * 256 + threadIdx.x;
    if (idx < nNodes) g_cursor[(int)idx] = 0;     // pre-zero for NEXT call's hist
    if (idx >= (long long)nEdges * 24) return;
    int w = (int)(idx % 24);
    long long e = idx / 24;
    int c = 2 * w;
    float f0 = 0.f, f1 = 0.f;
    if (c < EDGE_DIM)     f0 = ef[e * EDGE_DIM + c];
    if (c + 1 < EDGE_DIM) f1 = ef[e * EDGE_DIM + c + 1];
    __half2 h = __floats2half2_rn(f0, f1);
    int p = g_epos[e];
    g_efh[(size_t)p * 24 + w] = *reinterpret_cast<uint32_t*>(&h);
}

// ------------------------- conv edge GEMM (CSR-ordered tiles) ---------------
__device__ __forceinline__ void gatherAsync(uint32_t* sA, int nEdges, int t, int nTiles) {
    if (t >= nTiles) return;
    int j = threadIdx.x;
    int row = j >> 1, half = j & 1;
    int pos = (t << 7) + row;
    bool valid = pos < nEdges;
    int pc = valid ? pos : 0;
    int sz = valid ? 16 : 0;
    int2 nd = g_ecsr[pc];
    int node = half ? nd.y : nd.x;
    const char* hs = (const char*)(g_hh + (size_t)node * 32);
    uint32_t* rw = sA + row * ASTRIDE;
    uint32_t dh = smem_u32(rw + half * 32);
    #pragma unroll
    for (int i = 0; i < 8; i++) cp16(dh + i * 16, hs + i * 16, sz);
    const char* es = (const char*)(g_efh + (size_t)pc * 24 + half * 12);
    uint32_t de = smem_u32(rw + 64 + half * 12);
    #pragma unroll
    for (int i = 0; i < 3; i++) cp16(de + i * 16, es + i * 16, sz);
    CP_COMMIT();
}

__device__ __forceinline__ void kloop(float acc[2][4][4], uint32_t aAddr0,
                                      uint32_t aAddr1, const uint2* bBase, int nh) {
    #pragma unroll 1
    for (int bi = 0; bi < NCH; bi++) {
        uint2 b[4];
        const uint2* bp = bBase + bi * 512 + nh * 128;
        #pragma unroll
        for (int n4 = 0; n4 < 4; n4++) b[n4] = bp[n4 * 32];
        uint32_t a0[4], a1[4];
        ldsm4(a0, aAddr0 + bi * 32);
        ldsm4(a1, aAddr1 + bi * 32);
        #pragma unroll
        for (int n4 = 0; n4 < 4; n4++) {
            mma16816(acc[0][n4], a0, b[n4]);
            mma16816(acc[1][n4], a1, b[n4]);
        }
    }
}

__device__ __forceinline__ void statsEpi(float acc[2][4][4], int nh, int e0, int nEdges,
                                         int wm, int wn, int q, int r8,
                                         float* ssum, float* ssq) {
    #pragma unroll
    for (int mt = 0; mt < 2; mt++)
        #pragma unroll
        for (int n4 = 0; n4 < 4; n4++) {
            float c0 = acc[mt][n4][0], c1 = acc[mt][n4][1];
            float c2 = acc[mt][n4][2], c3 = acc[mt][n4][3];
            int s = nh * 8 + n4 * 2;
            ssum[s]     += c0 + c2;   ssum[s + 1] += c1 + c3;
            ssq[s]      += c0 * c0 + c2 * c2;
            ssq[s + 1]  += c1 * c1 + c3 * c3;
        }
    #pragma unroll
    for (int mt = 0; mt < 2; mt++)
        #pragma unroll
        for (int hf = 0; hf < 2; hf++) {
            int p = e0 + wm * 32 + mt * 16 + hf * 8 + r8;
            if (p < nEdges) {
                __half* base = g_zh + (size_t)p * OUTC + wn * 64 + nh * 32 + 2 * q;
                #pragma unroll
                for (int n4 = 0; n4 < 4; n4++) {
                    __half2 h = __floats2half2_rn(acc[mt][n4][2 * hf],
                                                  acc[mt][n4][2 * hf + 1]);
                    stcs32(base + n4 * 8, *reinterpret_cast<uint32_t*>(&h));
                }
            }
        }
}

__global__ void __launch_bounds__(256, 2)
conv_mma_kernel(int l, int nEdges, int nTiles) {
    extern __shared__ uint32_t sm[];
    uint32_t* sA = sm;
    uint2*    sB = (uint2*)(sm + AWORDS);

    const int tid = threadIdx.x, wid = tid >> 5, lane = tid & 31;
    const int q = lane & 3, r8 = lane >> 2;
    const int wm = wid & 3, wn = wid >> 2;

    gatherAsync(sA, nEdges, blockIdx.x, nTiles);
    const uint2* bf = g_bfrag + (size_t)l * BU2;
    for (int i = tid; i < BU2 / 2; i += 256)
        ((uint4*)sB)[i] = ((const uint4*)bf)[i];

    float ssum[16], ssq[16];
    #pragma unroll
    for (int j = 0; j < 16; j++) { ssum[j] = 0.f; ssq[j] = 0.f; }

    CP_WAIT0();
    __syncthreads();

    const uint32_t sAb = smem_u32(sA);
    const uint32_t aAddr0 = sAb + (uint32_t)((wm * 32 + (lane & 15)) * (ASTRIDE * 4)) +
                            ((lane >> 4) << 4);
    const uint32_t aAddr1 = aAddr0 + 16 * (ASTRIDE * 4);
    const uint2* bBase = sB + (wn * 8) * 32 + lane;

    for (int t = blockIdx.x; t < nTiles; t += gridDim.x) {
        const int e0 = t << 7;
        {   // N half 0
            float acc[2][4][4];
            #pragma unroll
            for (int mt = 0; mt < 2; mt++)
                #pragma unroll
                for (int n4 = 0; n4 < 4; n4++)
                    #pragma unroll
                    for (int jj = 0; jj < 4; jj++) acc[mt][n4][jj] = 0.f;
            kloop(acc, aAddr0, aAddr1, bBase, 0);
            statsEpi(acc, 0, e0, nEdges, wm, wn, q, r8, ssum, ssq);
        }
        {   // N half 1 (+ prefetch next tile between MMA and epilogue)
            float acc[2][4][4];
            #pragma unroll
            for (int mt = 0; mt < 2; mt++)
                #pragma unroll
                for (int n4 = 0; n4 < 4; n4++)
                    #pragma unroll
                    for (int jj = 0; jj < 4; jj++) acc[mt][n4][jj] = 0.f;
            kloop(acc, aAddr0, aAddr1, bBase, 1);
            __syncthreads();
            gatherAsync(sA, nEdges, t + gridDim.x, nTiles);
            statsEpi(acc, 1, e0, nEdges, wm, wn, q, r8, ssum, ssq);
        }
        CP_WAIT0();
        __syncthreads();
    }

    #pragma unroll
    for (int j = 0; j < 16; j++) {
        #pragma unroll
        for (int ofs = 4; ofs < 32; ofs <<= 1) {
            ssum[j] += __shfl_xor_sync(0xffffffffu, ssum[j], ofs);
            ssq[j]  += __shfl_xor_sync(0xffffffffu, ssq[j], ofs);
        }
    }
    if (lane < 4) {
        #pragma unroll
        for (int nh = 0; nh < 2; nh++)
            #pragma unroll
            for (int n4 = 0; n4 < 4; n4++)
                #pragma unroll
                for (int jj = 0; jj < 2; jj++) {
                    int col = wn * 64 + nh * 32 + n4 * 8 + 2 * lane + jj;
                    atomicAdd(&g_sumL[l][col], ssum[nh * 8 + n4 * 2 + jj]);
                    atomicAdd(&g_sqL[l][col],  ssq[nh * 8 + n4 * 2 + jj]);
                }
    }
}

// ------------------------- CSR gate: inline BN coefs + streaming z ----------
__global__ void __launch_bounds__(256)
csr_gate_kernel(const int* __restrict__ gidArr, const float* __restrict__ gamma,
                const float* __restrict__ beta, float invE, int l,
                int nNodes, int doPool) {
    __shared__ float sc[2 * OUTC];
    {
        int c = threadIdx.x;
        if (c < OUTC) {
            float s = g_sumL[l][c], ss = g_sqL[l][c];
            float mean = s * invE;
            float var  = fmaf(-mean, mean, ss * invE);
            float a    = gamma[c] * rsqrtf(var + BN_EPS);
            sc[c]        = a;
            sc[OUTC + c] = fmaf(-mean, a, beta[c]);
        }
    }
    __syncthreads();

    int gw = blockIdx.x * 8 + (threadIdx.x >> 5);
    if (gw >= nNodes) return;
    int lane = threadIdx.x & 31;

    float sa0 = sc[2 * lane],             sa1 = sc[2 * lane + 1];
    float ha0 = sc[OUTC + 2 * lane],      ha1 = sc[OUTC + 2 * lane + 1];
    float sb0 = sc[64 + 2 * lane],        sb1 = sc[64 + 2 * lane + 1];
    float hb0 = sc[OUTC + 64 + 2 * lane], hb1 = sc[OUTC + 64 + 2 * lane + 1];

    int beg = g_rowstart[gw], end = g_rowstart[gw + 1];
    float a0 = 0.f, a1 = 0.f;
    const uint32_t* zr = (const uint32_t*)(g_zh) + (size_t)beg * 64;
    #pragma unroll 2
    for (int i = beg; i < end; i++, zr += 64) {
        uint32_t A = ldcs32(zr + lane);
        uint32_t B = ldcs32(zr + 32 + lane);
        __half2 ha = *reinterpret_cast<__half2*>(&A);
        __half2 hb = *reinterpret_cast<__half2*>(&B);
        float na0 = fmaf(__low2float(ha),  sa0, ha0);
        float na1 = fmaf(__high2float(ha), sa1, ha1);
        float nb0 = fmaf(__low2float(hb),  sb0, hb0);
        float nb1 = fmaf(__high2float(hb), sb1, hb1);
        a0 += fsig(na0) * fsp(nb0);
        a1 += fsig(na1) * fsp(nb1);
    }
    float2* hp = (float2*)(g_h + (size_t)gw * HDIM) + lane;
    float2 hv = *hp;
    hv.x += a0; hv.y += a1;
    *hp = hv;
    __half2 hh = __floats2half2_rn(hv.x, hv.y);
    g_hh[(size_t)gw * 32 + lane] = *reinterpret_cast<uint32_t*>(&hh);
    if (doPool) {
        int g = gidArr[gw];
        float* pr = g_pool + (size_t)g * HDIM + 2 * lane;
        asm volatile("red.global.add.v2.f32 [%0], {%1, %2};"
                     :: "l"(pr), "f"(hv.x), "f"(hv.y) : "memory");
        if (lane == 0) atomicAdd(&g_cnt[g], 1.0f);
    }
}

// ------------------------- prediction head (self-zeroing pool + stats) ------
__global__ void __launch_bounds__(PRED_H)
head_kernel(const float* __restrict__ fcW, const float* __restrict__ fcb,
            const float* __restrict__ outW, const float* __restrict__ outb,
            float* __restrict__ out) {
    __shared__ float sp[HDIM];
    __shared__ float red[PRED_H];
    int g = blockIdx.x, t = threadIdx.x;
    if (g < MAX_CONV) {                 // re-zero BN stats for next call
        g_sumL[g][t] = 0.f;
        g_sqL[g][t]  = 0.f;
    }
    if (t < HDIM) {
        float c = g_cnt[g];
        sp[t] = g_pool[(size_t)g * HDIM + t] / fmaxf(c, 1.0f);
    }
    __syncthreads();
    float acc = fcb[t];
    #pragma unroll
    for (int k = 0; k < HDIM; k++) acc = fmaf(sp[k], fcW[k * PRED_H + t], acc);
    red[t] = fmaxf(acc, 0.f) + log1pf(expf(-fabsf(acc)));
    red[t] *= outW[t];
    __syncthreads();
    for (int sft = PRED_H / 2; sft > 0; sft >>= 1) {
        if (t < sft) red[t] += red[t + sft];
        __syncthreads();
    }
    if (t == 0) out[g] = red[0] + outb[0];
    __syncthreads();
    if (t < HDIM) g_pool[(size_t)g * HDIM + t] = 0.f;
    if (t == HDIM) g_cnt[g] = 0.f;
}

// ------------------------- launch -------------------------------------------
extern "C" void kernel_launch(void* const* d_in, const int* in_sizes, int n_in,
                              void* d_out, int out_size) {
    const float* node_feats = (const float*)d_in[0];
    const int*   edge_index = (const int*)d_in[1];
    const float* edge_feats = (const float*)d_in[2];
    const int*   graph_id   = (const int*)d_in[3];
    const float* emb_W      = (const float*)d_in[4];
    const float* emb_b      = (const float*)d_in[5];
    const float* conv_W     = (const float*)d_in[6];
    // d_in[7] = conv_b: zeros; constant bias cancels exactly in BN.
    const float* bn_gamma   = (const float*)d_in[8];
    const float* bn_beta    = (const float*)d_in[9];
    const float* fc_W       = (const float*)d_in[10];
    const float* fc_b       = (const float*)d_in[11];
    const float* out_W      = (const float*)d_in[12];
    const float* out_b      = (const float*)d_in[13];

    int nNodes  = in_sizes[0] / NODE_DIM;
    int nEdges  = in_sizes[1] / 2;
    int nConv   = in_sizes[6] / (KD * OUTC);

    int nsm = 148;
    cudaDeviceGetAttribute(&nsm, cudaDevAttrMultiProcessorCount, 0);

    size_t convSmem = (size_t)SMEM_WORDS * 4;   // 92160 B
    cudaFuncSetAttribute(conv_mma_kernel,
                         cudaFuncAttributeMaxDynamicSharedMemorySize, (int)convSmem);

    int eb = (nEdges + 255) / 256;
    // 1. fused embedding + histogram (cursor pre-zeroed by previous call / static init)
    emb_hist_kernel<<<EMB_BLOCKS + eb, 256>>>(node_feats, emb_W, emb_b,
                                              edge_index, nNodes, nEdges);
    // 2-4. scan
    int nb1 = (nNodes + 1023) / 1024;
    scan1_kernel<<<nb1, 1024>>>(nNodes);
    scan2_kernel<<<1, 1024>>>(nb1);
    scan3_kernel<<<nb1, 1024>>>(nNodes, nEdges);
    // 5. scatter (builds epos + ecsr)
    scatter_kernel<<<eb, 256>>>(edge_index, nEdges);
    // 6. efsplit (CSR-permuted) + all-layer bfrag + cursor re-zero
    {
        long long tot = (long long)nEdges * 24;
        int efBlocks = (int)((tot + 255) / 256);
        int bfragTotal = nConv * BU2;
        int bfBlocks = (bfragTotal + 255) / 256;
        prep_kernel<<<efBlocks + bfBlocks, 256>>>(edge_feats, conv_W,
                                                  nEdges, nNodes, efBlocks, bfragTotal);
    }

    int nTiles = (nEdges + 127) / 128;
    float invE = 1.0f / (float)nEdges;
    int gateBlocks = (nNodes + 7) / 8;
    for (int l = 0; l < nConv; l++) {
        conv_mma_kernel<<<2 * nsm, 256, convSmem>>>(l, nEdges, nTiles);
        csr_gate_kernel<<<gateBlocks, 256>>>(graph_id, bn_gamma + l * OUTC,
                                             bn_beta + l * OUTC, invE, l,
                                             nNodes, l == nConv - 1);
    }

    head_kernel<<<out_size, PRED_H>>>(fc_W, fc_b, out_W, out_b, (float*)d_out);
}

// round 17
// speedup vs baseline: 1.3710x; 1.1368x over previous
#include <cuda_runtime.h>
#include <cuda_bf16.h>
#include <cuda_fp16.h>
#include <cstdint>

#define HDIM 64
#define NODE_DIM 92
#define EDGE_DIM 41
#define KD 169            // 2H + EDGE_DIM
#define OUTC 128          // 2H
#define PRED_H 128
#define BN_EPS 1e-5f
#define MAX_NODES 100000
#define MAX_EDGES 1600000
#define MAX_GRAPHS 4096
#define MAX_CONV 3
#define EMB_BLOCKS 2048

#define NCH 11            // k16 chunks (K=176 padded)
#define ASTRIDE 92        // A smem row stride (u32 words): 88 data + 4 pad
#define AWORDS (128 * ASTRIDE)               // 47104 B
#define BU2    (NCH * 16 * 32)               // 5632 uint2 = 45056 B
#define SMEM_WORDS (AWORDS + 2 * BU2 + 4)    // + mbarrier slot
#define TILE_TX 45056                         // 128 * (128 + 128 + 96) bytes

// ------------------------- device scratch ------------------------------------
__device__ float  g_h[MAX_NODES * HDIM];
__device__ __half g_zh[(size_t)MAX_EDGES * OUTC];   // CSR-ordered pre-BN activations
__device__ float  g_sumL[MAX_CONV][OUTC];           // per-layer BN stats (zeroed in head)
__device__ float  g_sqL[MAX_CONV][OUTC];
__device__ float  g_pool[MAX_GRAPHS * HDIM];
__device__ float  g_cnt[MAX_GRAPHS];
__device__ __align__(16) uint2    g_bfrag[MAX_CONV * BU2];
__device__ __align__(16) uint32_t g_hh[(size_t)MAX_NODES * 32];   // h as fp16x2
__device__ __align__(16) uint32_t g_efh[(size_t)MAX_EDGES * 24];  // ef fp16x2, CSR order
// CSR
__device__ int  g_rowstart[MAX_NODES + 1];
__device__ int  g_cursor[MAX_NODES];
__device__ int  g_epos[MAX_EDGES];                  // edge -> CSR position
__device__ int2 g_ecsr[MAX_EDGES];                  // CSR position -> (src, dst)
__device__ int  g_bsum[1024];

// ------------------------- helpers ------------------------------------------
__device__ __forceinline__ float fsig(float x) {
    float t;
    asm("tanh.approx.f32 %0, %1;" : "=f"(t) : "f"(0.5f * x));
    return fmaf(0.5f, t, 0.5f);
}
__device__ __forceinline__ float fsp(float x) {
    float t = __expf(-fabsf(x));
    return fmaxf(x, 0.f) + __logf(1.f + t);
}

__device__ __forceinline__ void mma16816(float* d, const uint32_t* a, uint2 b) {
    asm volatile("mma.sync.aligned.m16n8k16.row.col.f32.f16.f16.f32 "
                 "{%0,%1,%2,%3}, {%4,%5,%6,%7}, {%8,%9}, {%0,%1,%2,%3};"
                 : "+f"(d[0]), "+f"(d[1]), "+f"(d[2]), "+f"(d[3])
                 : "r"(a[0]), "r"(a[1]), "r"(a[2]), "r"(a[3]), "r"(b.x), "r"(b.y));
}
__device__ __forceinline__ void ldsm4(uint32_t* a, uint32_t addr) {
    asm volatile("ldmatrix.sync.aligned.m8n8.x4.shared.b16 {%0,%1,%2,%3}, [%4];"
                 : "=r"(a[0]), "=r"(a[1]), "=r"(a[2]), "=r"(a[3]) : "r"(addr));
}
__device__ __forceinline__ uint32_t smem_u32(const void* p) {
    uint32_t a;
    asm("{ .reg .u64 t; cvta.to.shared.u64 t, %1; cvt.u32.u64 %0, t; }" : "=r"(a) : "l"(p));
    return a;
}
__device__ __forceinline__ void cp16(uint32_t dst, const void* src, int sz) {
    asm volatile("cp.async.cg.shared.global [%0], [%1], 16, %2;"
                 :: "r"(dst), "l"(src), "r"(sz) : "memory");
}
#define CP_COMMIT() asm volatile("cp.async.commit_group;" ::: "memory")
#define CP_WAIT0()  asm volatile("cp.async.wait_group 0;" ::: "memory")
__device__ __forceinline__ void cpbulk(uint32_t dst, const void* src, uint32_t bytes,
                                       uint32_t mbar) {
    asm volatile("cp.async.bulk.shared::cta.global.mbarrier::complete_tx::bytes "
                 "[%0], [%1], %2, [%3];"
                 :: "r"(dst), "l"(src), "r"(bytes), "r"(mbar) : "memory");
}
#define MBARRIER_INIT(mb, c) \
    asm volatile("mbarrier.init.shared.b64 [%0], %1;" :: "r"((uint32_t)(mb)), \
                 "r"((uint32_t)(c)) : "memory")
#define MBARRIER_EXPECT_TX(mb, tx) \
    asm volatile("mbarrier.arrive.expect_tx.shared.b64 _, [%0], %1;" \
                 :: "r"((uint32_t)(mb)), "r"((uint32_t)(tx)) : "memory")
#define MBARRIER_WAIT_PARITY(mb, ph) do {                                          \
    uint32_t _m = (uint32_t)(mb); uint32_t _p = (uint32_t)(ph); uint32_t _d;       \
    asm volatile("{\n\t.reg .pred p;\n\t"                                          \
        "mbarrier.try_wait.parity.acquire.cta.shared::cta.b64 p, [%1], %2;\n\t"    \
        "selp.b32 %0, 1, 0, p;\n\t}" : "=r"(_d) : "r"(_m), "r"(_p) : "memory");    \
    if (!_d) {                                                                     \
        asm volatile("{\n\t.reg .pred P1;\n\tWL_%=:\n\t"                           \
            "mbarrier.try_wait.parity.acquire.cta.shared::cta.b64 P1, [%0], %1, 0x989680;\n\t" \
            "@P1 bra.uni WD_%=;\n\tbra.uni WL_%=;\n\tWD_%=:\n\t}"                  \
            :: "r"(_m), "r"(_p) : "memory");                                       \
    }                                                                              \
} while (0)
__device__ __forceinline__ void stcs32(void* p, uint32_t v) {
    asm volatile("st.global.cs.u32 [%0], %1;" :: "l"(p), "r"(v) : "memory");
}
__device__ __forceinline__ uint32_t ldcs32(const void* p) {
    uint32_t v;
    asm volatile("ld.global.cs.u32 %0, [%1];" : "=r"(v) : "l"(p));
    return v;
}

// ------------------------- 1. fused embedding + edge histogram --------------
__global__ void __launch_bounds__(256)
emb_hist_kernel(const float* __restrict__ nf, const float* __restrict__ Wm,
                const float* __restrict__ b, const int* __restrict__ ei,
                int nNodes, int nEdges) {
    if ((int)blockIdx.x >= EMB_BLOCKS) {
        int e = (blockIdx.x - EMB_BLOCKS) * 256 + threadIdx.x;
        if (e < nEdges) atomicAdd(&g_cursor[ei[e]], 1);
        return;
    }
    __shared__ float sW[NODE_DIM * HDIM];
    __shared__ float sXn[8][NODE_DIM];
    for (int i = threadIdx.x; i < NODE_DIM * HDIM; i += 256) sW[i] = Wm[i];
    __syncthreads();
    int wid = threadIdx.x >> 5, lane = threadIdx.x & 31;
    int gw = (blockIdx.x * 256 + threadIdx.x) >> 5;
    int nW = (EMB_BLOCKS * 256) >> 5;
    float b0 = b[2 * lane], b1 = b[2 * lane + 1];
    for (int n = gw; n < nNodes; n += nW) {
        __syncwarp();
        for (int k = lane; k < NODE_DIM; k += 32) sXn[wid][k] = nf[(size_t)n * NODE_DIM + k];
        __syncwarp();
        float a0 = b0, a1 = b1;
        #pragma unroll 4
        for (int k = 0; k < NODE_DIM; k++) {
            float xv = sXn[wid][k];
            float2 w = ((const float2*)sW)[k * 32 + lane];
            a0 = fmaf(xv, w.x, a0);
            a1 = fmaf(xv, w.y, a1);
        }
        ((float2*)(g_h + (size_t)n * HDIM))[lane] = make_float2(a0, a1);
        __half2 h = __floats2half2_rn(a0, a1);
        g_hh[(size_t)n * 32 + lane] = *reinterpret_cast<uint32_t*>(&h);
    }
}

// ------------------------- CSR scan + scatter --------------------------------
__global__ void __launch_bounds__(1024)
scan1_kernel(int n) {
    __shared__ int wsum[32];
    int tid = threadIdx.x;
    int i = blockIdx.x * 1024 + tid;
    int c = (i < n) ? g_cursor[i] : 0;
    int v = c;
    #pragma unroll
    for (int o = 1; o < 32; o <<= 1) {
        int t = __shfl_up_sync(0xffffffffu, v, o);
        if ((tid & 31) >= o) v += t;
    }
    if ((tid & 31) == 31) wsum[tid >> 5] = v;
    __syncthreads();
    if (tid < 32) {
        int s = wsum[tid];
        #pragma unroll
        for (int o = 1; o < 32; o <<= 1) {
            int t = __shfl_up_sync(0xffffffffu, s, o);
            if (tid >= o) s += t;
        }
        wsum[tid] = s;
    }
    __syncthreads();
    int incl = v + ((tid >= 32) ? wsum[(tid >> 5) - 1] : 0);
    if (i < n) g_rowstart[i] = incl - c;
    if (tid == 1023) g_bsum[blockIdx.x] = incl;
}
__global__ void __launch_bounds__(1024)
scan2_kernel(int nb) {
    __shared__ int wsum[32];
    int tid = threadIdx.x;
    int v = (tid < nb) ? g_bsum[tid] : 0;
    #pragma unroll
    for (int o = 1; o < 32; o <<= 1) {
        int t = __shfl_up_sync(0xffffffffu, v, o);
        if ((tid & 31) >= o) v += t;
    }
    if ((tid & 31) == 31) wsum[tid >> 5] = v;
    __syncthreads();
    if (tid < 32) {
        int s = wsum[tid];
        #pragma unroll
        for (int o = 1; o < 32; o <<= 1) {
            int t = __shfl_up_sync(0xffffffffu, s, o);
            if (tid >= o) s += t;
        }
        wsum[tid] = s;
    }
    __syncthreads();
    int incl = v + ((tid >= 32) ? wsum[(tid >> 5) - 1] : 0);
    if (tid < nb) g_bsum[tid] = incl;
}
__global__ void __launch_bounds__(1024)
scan3_kernel(int n, int nEdges) {
    int i = blockIdx.x * 1024 + threadIdx.x;
    if (i >= n) return;
    int off = blockIdx.x ? g_bsum[blockIdx.x - 1] : 0;
    int ex = g_rowstart[i] + off;
    g_rowstart[i] = ex;
    g_cursor[i] = ex;
    if (i == n - 1) g_rowstart[n] = nEdges;
}
__global__ void scatter_kernel(const int* __restrict__ ei, int nEdges) {
    int e = blockIdx.x * 256 + threadIdx.x;
    if (e >= nEdges) return;
    int s = ei[e], d = ei[nEdges + e];
    int p = atomicAdd(&g_cursor[s], 1);
    g_epos[e] = p;
    g_ecsr[p] = make_int2(s, d);
}

// ------------------------- prep: efsplit (CSR) + bfrag + cursor re-zero -----
__global__ void __launch_bounds__(256)
prep_kernel(const float* __restrict__ ef, const float* __restrict__ W,
            int nEdges, int nNodes, int efBlocks, int bfragTotal) {
    if ((int)blockIdx.x >= efBlocks) {
        int idx = (blockIdx.x - efBlocks) * 256 + threadIdx.x;
        if (idx >= bfragTotal) return;
        int l = idx / BU2, r = idx % BU2;
        int lane = r & 31;
        int nt   = (r >> 5) & 15;
        int bi   = r >> 9;
        const float* Wl = W + (size_t)l * KD * OUTC;
        int n    = nt * 8 + (lane >> 2);
        int k0   = bi * 16 + (lane & 3) * 2;
        uint32_t out[2];
        #pragma unroll
        for (int half = 0; half < 2; half++) {
            float w0 = 0.f, w1 = 0.f;
            int ka = k0 + half * 8, kb = ka + 1;
            if (ka < KD) w0 = Wl[ka * OUTC + n];
            if (kb < KD) w1 = Wl[kb * OUTC + n];
            __half2 h = __floats2half2_rn(w0, w1);
            out[half] = *reinterpret_cast<uint32_t*>(&h);
        }
        g_bfrag[idx] = make_uint2(out[0], out[1]);
        return;
    }
    long long idx = (long long)blockIdx.x * 256 + threadIdx.x;
    if (idx < nNodes) g_cursor[(int)idx] = 0;     // pre-zero for NEXT call's hist
    if (idx >= (long long)nEdges * 24) return;
    int w = (int)(idx % 24);
    long long e = idx / 24;
    int c = 2 * w;
    float f0 = 0.f, f1 = 0.f;
    if (c < EDGE_DIM)     f0 = ef[e * EDGE_DIM + c];
    if (c + 1 < EDGE_DIM) f1 = ef[e * EDGE_DIM + c + 1];
    __half2 h = __floats2half2_rn(f0, f1);
    int p = g_epos[e];
    g_efh[(size_t)p * 24 + w] = *reinterpret_cast<uint32_t*>(&h);
}

// ------------------------- conv edge GEMM (bulk-copy gather) ----------------
// full tile: 3 cp.async.bulk per row (src h 128B, dst h 128B, ef 96B), mbarrier
// completion. partial tail tile: cp16 zero-fill path + expect_tx(0).
__device__ __forceinline__ void gatherIssue(uint32_t* sA, uint32_t sA_u, uint32_t mbar,
                                            int nEdges, int t, int nTiles) {
    if (t >= nTiles) return;
    const int e0 = t << 7;
    const bool full = (e0 + 128 <= nEdges);
    if (threadIdx.x == 0) MBARRIER_EXPECT_TX(mbar, full ? TILE_TX : 0u);
    int j = threadIdx.x;
    if (full) {
        if (j < 128) {
            int pos = e0 + j;
            int2 nd = g_ecsr[pos];
            uint32_t dst = sA_u + (uint32_t)j * (ASTRIDE * 4);
            cpbulk(dst, g_hh + (size_t)nd.x * 32, 128, mbar);
            cpbulk(dst + 256, g_efh + (size_t)pos * 24, 96, mbar);
        } else {
            int row = j - 128;
            int pos = e0 + row;
            int2 nd = g_ecsr[pos];
            cpbulk(sA_u + (uint32_t)row * (ASTRIDE * 4) + 128,
                   g_hh + (size_t)nd.y * 32, 128, mbar);
        }
    } else {
        int row = j >> 1, half = j & 1;
        int pos = e0 + row;
        bool valid = pos < nEdges;
        int pc = valid ? pos : 0;
        int sz = valid ? 16 : 0;
        int2 nd = g_ecsr[pc];
        int node = half ? nd.y : nd.x;
        const char* hs = (const char*)(g_hh + (size_t)node * 32);
        uint32_t* rw = sA + row * ASTRIDE;
        uint32_t dh = smem_u32(rw + half * 32);
        #pragma unroll
        for (int i = 0; i < 8; i++) cp16(dh + i * 16, hs + i * 16, sz);
        const char* es = (const char*)(g_efh + (size_t)pc * 24 + half * 12);
        uint32_t de = smem_u32(rw + 64 + half * 12);
        #pragma unroll
        for (int i = 0; i < 3; i++) cp16(de + i * 16, es + i * 16, sz);
        CP_COMMIT();
    }
}

__device__ __forceinline__ void kloop(float acc[2][4][4], uint32_t aAddr0,
                                      uint32_t aAddr1, const uint2* bBase, int nh) {
    #pragma unroll 1
    for (int bi = 0; bi < NCH; bi++) {
        uint2 b[4];
        const uint2* bp = bBase + bi * 512 + nh * 128;
        #pragma unroll
        for (int n4 = 0; n4 < 4; n4++) b[n4] = bp[n4 * 32];
        uint32_t a0[4], a1[4];
        ldsm4(a0, aAddr0 + bi * 32);
        ldsm4(a1, aAddr1 + bi * 32);
        #pragma unroll
        for (int n4 = 0; n4 < 4; n4++) {
            mma16816(acc[0][n4], a0, b[n4]);
            mma16816(acc[1][n4], a1, b[n4]);
        }
    }
}

__device__ __forceinline__ void statsEpi(float acc[2][4][4], int nh, int e0, int nEdges,
                                         bool full, int wm, int wn, int q, int r8,
                                         float* ssum, float* ssq) {
    #pragma unroll
    for (int mt = 0; mt < 2; mt++)
        #pragma unroll
        for (int n4 = 0; n4 < 4; n4++) {
            float c0 = acc[mt][n4][0], c1 = acc[mt][n4][1];
            float c2 = acc[mt][n4][2], c3 = acc[mt][n4][3];
            int s = nh * 8 + n4 * 2;
            ssum[s]     += c0 + c2;   ssum[s + 1] += c1 + c3;
            ssq[s]      += c0 * c0 + c2 * c2;
            ssq[s + 1]  += c1 * c1 + c3 * c3;
        }
    #pragma unroll
    for (int mt = 0; mt < 2; mt++)
        #pragma unroll
        for (int hf = 0; hf < 2; hf++) {
            int p = e0 + wm * 32 + mt * 16 + hf * 8 + r8;
            if (full || p < nEdges) {
                __half* base = g_zh + (size_t)p * OUTC + wn * 64 + nh * 32 + 2 * q;
                #pragma unroll
                for (int n4 = 0; n4 < 4; n4++) {
                    __half2 h = __floats2half2_rn(acc[mt][n4][2 * hf],
                                                  acc[mt][n4][2 * hf + 1]);
                    stcs32(base + n4 * 8, *reinterpret_cast<uint32_t*>(&h));
                }
            }
        }
}

__global__ void __launch_bounds__(256, 2)
conv_mma_kernel(int l, int nEdges, int nTiles) {
    extern __shared__ uint32_t sm[];
    uint32_t* sA = sm;
    uint2*    sB = (uint2*)(sm + AWORDS);
    const uint32_t sA_u = smem_u32(sA);
    const uint32_t mbar = smem_u32(sm + AWORDS + 2 * BU2);

    const int tid = threadIdx.x, wid = tid >> 5, lane = tid & 31;
    const int q = lane & 3, r8 = lane >> 2;
    const int wm = wid & 3, wn = wid >> 2;

    if (tid == 0) MBARRIER_INIT(mbar, 1);
    const uint2* bf = g_bfrag + (size_t)l * BU2;
    for (int i = tid; i < BU2 / 2; i += 256)
        ((uint4*)sB)[i] = ((const uint4*)bf)[i];
    __syncthreads();                     // mbar init visible before any arrive

    gatherIssue(sA, sA_u, mbar, nEdges, blockIdx.x, nTiles);

    float ssum[16], ssq[16];
    #pragma unroll
    for (int j = 0; j < 16; j++) { ssum[j] = 0.f; ssq[j] = 0.f; }

    const uint32_t aAddr0 = sA_u + (uint32_t)((wm * 32 + (lane & 15)) * (ASTRIDE * 4)) +
                            ((lane >> 4) << 4);
    const uint32_t aAddr1 = aAddr0 + 16 * (ASTRIDE * 4);
    const uint2* bBase = sB + (wn * 8) * 32 + lane;

    unsigned ph = 0;
    for (int t = blockIdx.x; t < nTiles; t += gridDim.x) {
        MBARRIER_WAIT_PARITY(mbar, ph);
        ph ^= 1;
        CP_WAIT0();
        __syncthreads();                 // A tile visible to all warps

        const int e0 = t << 7;
        const bool full = (e0 + 128 <= nEdges);
        {   // N half 0
            float acc[2][4][4];
            #pragma unroll
            for (int mt = 0; mt < 2; mt++)
                #pragma unroll
                for (int n4 = 0; n4 < 4; n4++)
                    #pragma unroll
                    for (int jj = 0; jj < 4; jj++) acc[mt][n4][jj] = 0.f;
            kloop(acc, aAddr0, aAddr1, bBase, 0);
            statsEpi(acc, 0, e0, nEdges, full, wm, wn, q, r8, ssum, ssq);
        }
        {   // N half 1 (+ prefetch next tile between MMA and epilogue)
            float acc[2][4][4];
            #pragma unroll
            for (int mt = 0; mt < 2; mt++)
                #pragma unroll
                for (int n4 = 0; n4 < 4; n4++)
                    #pragma unroll
                    for (int jj = 0; jj < 4; jj++) acc[mt][n4][jj] = 0.f;
            kloop(acc, aAddr0, aAddr1, bBase, 1);
            __syncthreads();             // all A reads of this tile complete
            gatherIssue(sA, sA_u, mbar, nEdges, t + gridDim.x, nTiles);
            statsEpi(acc, 1, e0, nEdges, full, wm, wn, q, r8, ssum, ssq);
        }
    }

    #pragma unroll
    for (int j = 0; j < 16; j++) {
        #pragma unroll
        for (int ofs = 4; ofs < 32; ofs <<= 1) {
            ssum[j] += __shfl_xor_sync(0xffffffffu, ssum[j], ofs);
            ssq[j]  += __shfl_xor_sync(0xffffffffu, ssq[j], ofs);
        }
    }
    if (lane < 4) {
        #pragma unroll
        for (int nh = 0; nh < 2; nh++)
            #pragma unroll
            for (int n4 = 0; n4 < 4; n4++)
                #pragma unroll
                for (int jj = 0; jj < 2; jj++) {
                    int col = wn * 64 + nh * 32 + n4 * 8 + 2 * lane + jj;
                    atomicAdd(&g_sumL[l][col], ssum[nh * 8 + n4 * 2 + jj]);
                    atomicAdd(&g_sqL[l][col],  ssq[nh * 8 + n4 * 2 + jj]);
                }
    }
}

// ------------------------- CSR gate: inline BN coefs + streaming z ----------
__global__ void __launch_bounds__(256)
csr_gate_kernel(const int* __restrict__ gidArr, const float* __restrict__ gamma,
                const float* __restrict__ beta, float invE, int l,
                int nNodes, int doPool) {
    __shared__ float sc[2 * OUTC];
    {
        int c = threadIdx.x;
        if (c < OUTC) {
            float s = g_sumL[l][c], ss = g_sqL[l][c];
            float mean = s * invE;
            float var  = fmaf(-mean, mean, ss * invE);
            float a    = gamma[c] * rsqrtf(var + BN_EPS);
            sc[c]        = a;
            sc[OUTC + c] = fmaf(-mean, a, beta[c]);
        }
    }
    __syncthreads();

    int gw = blockIdx.x * 8 + (threadIdx.x >> 5);
    if (gw >= nNodes) return;
    int lane = threadIdx.x & 31;

    float sa0 = sc[2 * lane],             sa1 = sc[2 * lane + 1];
    float ha0 = sc[OUTC + 2 * lane],      ha1 = sc[OUTC + 2 * lane + 1];
    float sb0 = sc[64 + 2 * lane],        sb1 = sc[64 + 2 * lane + 1];
    float hb0 = sc[OUTC + 64 + 2 * lane], hb1 = sc[OUTC + 64 + 2 * lane + 1];

    int beg = g_rowstart[gw], end = g_rowstart[gw + 1];
    float a0 = 0.f, a1 = 0.f;
    const uint32_t* zr = (const uint32_t*)(g_zh) + (size_t)beg * 64;
    #pragma unroll 2
    for (int i = beg; i < end; i++, zr += 64) {
        uint32_t A = ldcs32(zr + lane);
        uint32_t B = ldcs32(zr + 32 + lane);
        __half2 ha = *reinterpret_cast<__half2*>(&A);
        __half2 hb = *reinterpret_cast<__half2*>(&B);
        float na0 = fmaf(__low2float(ha),  sa0, ha0);
        float na1 = fmaf(__high2float(ha), sa1, ha1);
        float nb0 = fmaf(__low2float(hb),  sb0, hb0);
        float nb1 = fmaf(__high2float(hb), sb1, hb1);
        a0 += fsig(na0) * fsp(nb0);
        a1 += fsig(na1) * fsp(nb1);
    }
    float2* hp = (float2*)(g_h + (size_t)gw * HDIM) + lane;
    float2 hv = *hp;
    hv.x += a0; hv.y += a1;
    *hp = hv;
    __half2 hh = __floats2half2_rn(hv.x, hv.y);
    g_hh[(size_t)gw * 32 + lane] = *reinterpret_cast<uint32_t*>(&hh);
    if (doPool) {
        int g = gidArr[gw];
        float* pr = g_pool + (size_t)g * HDIM + 2 * lane;
        asm volatile("red.global.add.v2.f32 [%0], {%1, %2};"
                     :: "l"(pr), "f"(hv.x), "f"(hv.y) : "memory");
        if (lane == 0) atomicAdd(&g_cnt[g], 1.0f);
    }
}

// ------------------------- prediction head (self-zeroing pool + stats) ------
__global__ void __launch_bounds__(PRED_H)
head_kernel(const float* __restrict__ fcW, const float* __restrict__ fcb,
            const float* __restrict__ outW, const float* __restrict__ outb,
            float* __restrict__ out) {
    __shared__ float sp[HDIM];
    __shared__ float red[PRED_H];
    int g = blockIdx.x, t = threadIdx.x;
    if (g < MAX_CONV) {                 // re-zero BN stats for next call
        g_sumL[g][t] = 0.f;
        g_sqL[g][t]  = 0.f;
    }
    if (t < HDIM) {
        float c = g_cnt[g];
        sp[t] = g_pool[(size_t)g * HDIM + t] / fmaxf(c, 1.0f);
    }
    __syncthreads();
    float acc = fcb[t];
    #pragma unroll
    for (int k = 0; k < HDIM; k++) acc = fmaf(sp[k], fcW[k * PRED_H + t], acc);
    red[t] = fmaxf(acc, 0.f) + log1pf(expf(-fabsf(acc)));
    red[t] *= outW[t];
    __syncthreads();
    for (int sft = PRED_H / 2; sft > 0; sft >>= 1) {
        if (t < sft) red[t] += red[t + sft];
        __syncthreads();
    }
    if (t == 0) out[g] = red[0] + outb[0];
    __syncthreads();
    if (t < HDIM) g_pool[(size_t)g * HDIM + t] = 0.f;
    if (t == HDIM) g_cnt[g] = 0.f;
}

// ------------------------- launch -------------------------------------------
extern "C" void kernel_launch(void* const* d_in, const int* in_sizes, int n_in,
                              void* d_out, int out_size) {
    const float* node_feats = (const float*)d_in[0];
    const int*   edge_index = (const int*)d_in[1];
    const float* edge_feats = (const float*)d_in[2];
    const int*   graph_id   = (const int*)d_in[3];
    const float* emb_W      = (const float*)d_in[4];
    const float* emb_b      = (const float*)d_in[5];
    const float* conv_W     = (const float*)d_in[6];
    // d_in[7] = conv_b: zeros; constant bias cancels exactly in BN.
    const float* bn_gamma   = (const float*)d_in[8];
    const float* bn_beta    = (const float*)d_in[9];
    const float* fc_W       = (const float*)d_in[10];
    const float* fc_b       = (const float*)d_in[11];
    const float* out_W      = (const float*)d_in[12];
    const float* out_b      = (const float*)d_in[13];

    int nNodes  = in_sizes[0] / NODE_DIM;
    int nEdges  = in_sizes[1] / 2;
    int nConv   = in_sizes[6] / (KD * OUTC);

    int nsm = 148;
    cudaDeviceGetAttribute(&nsm, cudaDevAttrMultiProcessorCount, 0);

    size_t convSmem = (size_t)SMEM_WORDS * 4;
    cudaFuncSetAttribute(conv_mma_kernel,
                         cudaFuncAttributeMaxDynamicSharedMemorySize, (int)convSmem);

    int eb = (nEdges + 255) / 256;
    emb_hist_kernel<<<EMB_BLOCKS + eb, 256>>>(node_feats, emb_W, emb_b,
                                              edge_index, nNodes, nEdges);
    int nb1 = (nNodes + 1023) / 1024;
    scan1_kernel<<<nb1, 1024>>>(nNodes);
    scan2_kernel<<<1, 1024>>>(nb1);
    scan3_kernel<<<nb1, 1024>>>(nNodes, nEdges);
    scatter_kernel<<<eb, 256>>>(edge_index, nEdges);
    {
        long long tot = (long long)nEdges * 24;
        int efBlocks = (int)((tot + 255) / 256);
        int bfragTotal = nConv * BU2;
        int bfBlocks = (bfragTotal + 255) / 256;
        prep_kernel<<<efBlocks + bfBlocks, 256>>>(edge_feats, conv_W,
                                                  nEdges, nNodes, efBlocks, bfragTotal);
    }

    int nTiles = (nEdges + 127) / 128;
    float invE = 1.0f / (float)nEdges;
    int gateBlocks = (nNodes + 7) / 8;
    for (int l = 0; l < nConv; l++) {
        conv_mma_kernel<<<2 * nsm, 256, convSmem>>>(l, nEdges, nTiles);
        csr_gate_kernel<<<gateBlocks, 256>>>(graph_id, bn_gamma + l * OUTC,
                                             bn_beta + l * OUTC, invE, l,
                                             nNodes, l == nConv - 1);
    }

    head_kernel<<<out_size, PRED_H>>>(fc_W, fc_b, out_W, out_b, (float*)d_out);
}